// round 12
// baseline (speedup 1.0000x reference)
#include <cuda_runtime.h>
#include <cuda_fp16.h>
#include <cstdint>
#include <math.h>

// Problem constants
#define B_      4
#define S_      4096
#define H_      1280
#define C_      2048
#define T_      77
#define I_      32
#define NHEADS  20
#define DH      64
#define L_      (T_ + I_)       // 109
#define LPAD    112             // K rows padded (mult of 16)
#define LPAD2   120             // V^T row length (240B rows -> conflict-free)
#define ROWS    (B_ * S_)       // 16384

// ---------------------------------------------------------------------------
// Scratch (device globals; zero-initialized; no allocations allowed)
// ---------------------------------------------------------------------------
__device__ __half g_q_hi[ROWS * H_];
__device__ __half g_q_lo[ROWS * H_];
__device__ __half g_att_hi[ROWS * H_];
__device__ __half g_att_lo[ROWS * H_];
__device__ __half g_hs_hi[ROWS * H_];
__device__ __half g_hs_lo[ROWS * H_];
__device__ __half g_wq[H_ * H_];          // Wq^T [N,K]
__device__ __half g_wo[H_ * H_];          // Wout^T [N,K]
__device__ __half g_k[B_ * LPAD * H_];    // K [b][l][n], rows 109..111 zero
__device__ __half g_vt[B_ * H_ * LPAD2];  // V^T [b][n][l], l 109..119 zero
__device__ int    g_ctr[2];               // persistent-gemm tile counters

// ---------------------------------------------------------------------------
// PTX helpers (sm_100 base target — NO tcgen05, which needs the 'a' variant)
// ---------------------------------------------------------------------------
#define CP_ASYNC_16(dst, src) \
    asm volatile("cp.async.cg.shared.global [%0], [%1], 16;" :: "r"(dst), "l"(src) : "memory")
#define CP_COMMIT() asm volatile("cp.async.commit_group;" ::: "memory")
#define CP_WAIT2()  asm volatile("cp.async.wait_group 2;" ::: "memory")
#define CP_WAIT0()  asm volatile("cp.async.wait_group 0;" ::: "memory")

__device__ __forceinline__ uint32_t smem_to_u32(const void* p) {
    uint32_t a;
    asm("{ .reg .u64 t; cvta.to.shared.u64 t, %1; cvt.u32.u64 %0, t; }"
        : "=r"(a) : "l"(p));
    return a;
}

__device__ __forceinline__ void ldsm_x4(uint32_t& r0, uint32_t& r1,
                                        uint32_t& r2, uint32_t& r3, uint32_t addr) {
    asm volatile("ldmatrix.sync.aligned.m8n8.x4.shared.b16 {%0,%1,%2,%3}, [%4];"
                 : "=r"(r0), "=r"(r1), "=r"(r2), "=r"(r3) : "r"(addr));
}

__device__ __forceinline__ void mma_f16(float* d, const uint32_t* a,
                                        uint32_t b0, uint32_t b1) {
    asm volatile(
        "mma.sync.aligned.m16n8k16.row.col.f32.f16.f16.f32 "
        "{%0,%1,%2,%3}, {%4,%5,%6,%7}, {%8,%9}, {%0,%1,%2,%3};"
        : "+f"(d[0]), "+f"(d[1]), "+f"(d[2]), "+f"(d[3])
        : "r"(a[0]), "r"(a[1]), "r"(a[2]), "r"(a[3]), "r"(b0), "r"(b1));
}

__device__ __forceinline__ uint32_t h2_bits(__half2 v) {
    return *reinterpret_cast<uint32_t*>(&v);
}

// fp16 two-term split of fp32 (exact to ~2^-22)
__device__ __forceinline__ void f16split(float x, __half& h, __half& l) {
    h = __float2half_rn(x);
    l = __float2half_rn(x - __half2float(h));
}

// ---------------------------------------------------------------------------
// Prep 1: elementwise split of hidden_states; block 0 resets tile counters
// ---------------------------------------------------------------------------
__global__ void __launch_bounds__(256) split_kernel(const float* __restrict__ src)
{
    if (blockIdx.x == 0 && threadIdx.x == 0) { g_ctr[0] = 0; g_ctr[1] = 0; }
    size_t i = ((size_t)blockIdx.x * 256 + threadIdx.x) * 4;
    float4 v = *(const float4*)(src + i);
    __half h0, l0, h1, l1, h2, l2, h3, l3;
    f16split(v.x, h0, l0); f16split(v.y, h1, l1);
    f16split(v.z, h2, l2); f16split(v.w, h3, l3);
    *(__half2*)(g_hs_hi + i)     = __half2(h0, h1);
    *(__half2*)(g_hs_hi + i + 2) = __half2(h2, h3);
    *(__half2*)(g_hs_lo + i)     = __half2(l0, l1);
    *(__half2*)(g_hs_lo + i + 2) = __half2(l2, l3);
}

// ---------------------------------------------------------------------------
// Prep 2: transpose Wq and Wout -> [N, K] single fp16
// ---------------------------------------------------------------------------
__global__ void __launch_bounds__(256) tsplit_kernel(const float* __restrict__ Wq,
                                                     const float* __restrict__ Wout)
{
    __shared__ float t[32][33];
    const float* W = blockIdx.z ? Wout : Wq;
    __half* dh = blockIdx.z ? g_wo : g_wq;
    int bx = blockIdx.x * 32, by = blockIdx.y * 32;
    int tx = threadIdx.x, ty = threadIdx.y;
    #pragma unroll
    for (int i = 0; i < 4; i++)
        t[ty + 8 * i][tx] = W[(size_t)(by + ty + 8 * i) * H_ + bx + tx];
    __syncthreads();
    #pragma unroll
    for (int i = 0; i < 4; i++) {
        size_t o = (size_t)(bx + ty + 8 * i) * H_ + by + tx;   // [n][k]
        dh[o] = __float2half_rn(t[tx][ty + 8 * i]);
    }
}

// ---------------------------------------------------------------------------
// KV build: fp32 SIMT GEMM; K -> [b][LPAD][H_] fp16, V -> V^T [b][H_][LPAD2].
// ---------------------------------------------------------------------------
__device__ __forceinline__ void kv_store(bool is_v, int b, int l, int n,
                                         const float* vals)
{
    if (!is_v) {
        size_t a = ((size_t)b * LPAD + l) * H_ + n;
        *(__half2*)(g_k + a)     = __half2(__float2half_rn(vals[0]), __float2half_rn(vals[1]));
        *(__half2*)(g_k + a + 2) = __half2(__float2half_rn(vals[2]), __float2half_rn(vals[3]));
    } else {
        #pragma unroll
        for (int j = 0; j < 4; j++)
            g_vt[((size_t)b * H_ + n + j) * LPAD2 + l] = __float2half_rn(vals[j]);
    }
}

__global__ void __launch_bounds__(256) kv_kernel(
    const float* __restrict__ ehs, const float* __restrict__ idemb,
    const float* __restrict__ Wk, const float* __restrict__ Wv,
    const float* __restrict__ Wid_k, const float* __restrict__ Wid_v)
{
    const int z = blockIdx.z;
    const bool is_id = (z >= 2);
    const bool is_v  = (z & 1);
    const float* A = is_id ? idemb : ehs;
    const float* W = is_id ? (is_v ? Wid_v : Wid_k) : (is_v ? Wv : Wk);
    const int Mloc = is_id ? (2 * I_) : (B_ * T_);

    const int m0 = blockIdx.y * 64;
    if (m0 >= Mloc) return;
    const int n0 = blockIdx.x * 64;

    __shared__ float As[16][68];
    __shared__ float Bs[16][64];

    const int tid  = threadIdx.x;
    const int arow = tid >> 2;
    const int ac4  = (tid & 3) * 4;
    const int brow = tid >> 4;
    const int bc4  = (tid & 15) * 4;
    const int tx   = tid & 15;
    const int ty   = tid >> 4;

    float acc[4][4];
    #pragma unroll
    for (int i = 0; i < 4; i++)
        #pragma unroll
        for (int j = 0; j < 4; j++) acc[i][j] = 0.f;

    for (int k0 = 0; k0 < C_; k0 += 16) {
        float4 av = make_float4(0.f, 0.f, 0.f, 0.f);
        if (m0 + arow < Mloc)
            av = *(const float4*)(A + (size_t)(m0 + arow) * C_ + k0 + ac4);
        float4 bv = *(const float4*)(W + (size_t)(k0 + brow) * H_ + n0 + bc4);
        __syncthreads();
        As[ac4 + 0][arow] = av.x;
        As[ac4 + 1][arow] = av.y;
        As[ac4 + 2][arow] = av.z;
        As[ac4 + 3][arow] = av.w;
        *(float4*)&Bs[brow][bc4] = bv;
        __syncthreads();
        #pragma unroll
        for (int kk = 0; kk < 16; kk++) {
            float4 a = *(const float4*)&As[kk][ty * 4];
            float4 b = *(const float4*)&Bs[kk][tx * 4];
            float am[4] = {a.x, a.y, a.z, a.w};
            float bn[4] = {b.x, b.y, b.z, b.w};
            #pragma unroll
            for (int i = 0; i < 4; i++)
                #pragma unroll
                for (int j = 0; j < 4; j++)
                    acc[i][j] += am[i] * bn[j];
        }
    }

    #pragma unroll
    for (int i = 0; i < 4; i++) {
        int r = m0 + ty * 4 + i;
        if (r >= Mloc) continue;
        if (!is_id) {
            int batch = r / T_, pos = r % T_;
            kv_store(is_v, batch, pos, n0 + tx * 4, acc[i]);
        } else {
            int hb = r >> 5, ii = r & 31;
            kv_store(is_v, hb,     T_ + ii, n0 + tx * 4, acc[i]);
            kv_store(is_v, hb + 2, T_ + ii, n0 + tx * 4, acc[i]);
        }
    }
}

// ---------------------------------------------------------------------------
// HMMA fp16x2 GEMM, persistent (R12): 296 CTAs (2/SM) dynamically steal
// 128x128 tiles via atomicAdd on g_ctr[MODE] — kills the 4.32-wave ceil-5
// quantization tail (~14%). Per-tile: proven 4-stage cp.async pipeline,
// R6 ordering. MODE 0: hs@Wq -> q splits. MODE 1: att@Wo + bias -> Cp.
// ---------------------------------------------------------------------------
#define GK       H_          // 1280
#define GN       H_          // 1280
#define BK       32
#define NIT      (GK / BK)   // 40
#define TILE_B   (128 * 64)  // 8192 B
#define STAGE_B  (3 * TILE_B)   // Ah, Al, B = 24576 B
#define NSTAGE   4
#define NTILE_M  (ROWS / 128)   // 128
#define NTILE_N  (GN / 128)     // 10
#define NTILES   (NTILE_M * NTILE_N)  // 1280
#define GEMM_CTAS 296

__device__ __forceinline__ uint32_t swz(int row, int chunk) {
    return (uint32_t)(row * 64 + ((chunk ^ ((row >> 1) & 3)) << 4));
}

__device__ __forceinline__ void fill_tile(uint32_t dst, const __half* src,
                                          int k0, int tid)
{
    #pragma unroll
    for (int i = 0; i < 2; i++) {
        int idx = i * 256 + tid;
        int row = idx >> 2;
        int c   = idx & 3;
        CP_ASYNC_16(dst + swz(row, c),
                    src + (size_t)row * GK + k0 + c * 8);
    }
}

template<int MODE>
__global__ void __launch_bounds__(256, 2) gemm_hmma(
    const float* __restrict__ bias, float* __restrict__ Cp)
{
    const __half* Ahi = (MODE == 0) ? g_hs_hi : g_att_hi;
    const __half* Alo = (MODE == 0) ? g_hs_lo : g_att_lo;
    const __half* Bw  = (MODE == 0) ? g_wq : g_wo;

    extern __shared__ char smem[];
    const uint32_t sb = smem_to_u32(smem);
    __shared__ int s_tile;

    const int tid  = threadIdx.x;
    const int wid  = tid >> 5;
    const int lane = tid & 31;
    const int wm   = wid >> 1;
    const int wn   = wid & 1;

    const int a_row_off = (lane & 7) + ((lane >> 3) & 1) * 8;
    const int a_half    = lane >> 4;
    const int b_row_off = (lane & 7) + ((lane >> 4) & 1) * 8;
    const int b_half    = (lane >> 3) & 1;
    const int gid = lane >> 2, tig = lane & 3;

    for (;;) {
        if (tid == 0) s_tile = atomicAdd(&g_ctr[MODE], 1);
        __syncthreads();                 // broadcasts s_tile; joins all warps
        const int t = s_tile;
        if (t >= NTILES) break;
        CP_WAIT0();                      // clear stale groups from prior tile

        const int m0 = (t / NTILE_N) * 128;
        const int n0 = (t % NTILE_N) * 128;
        const __half* aH = Ahi + (size_t)m0 * GK;
        const __half* aL = Alo + (size_t)m0 * GK;
        const __half* bW = Bw  + (size_t)n0 * GK;

        float acc[2][8][4];
        #pragma unroll
        for (int mt = 0; mt < 2; mt++)
            #pragma unroll
            for (int nt = 0; nt < 8; nt++)
                #pragma unroll
                for (int c = 0; c < 4; c++) acc[mt][nt][c] = 0.f;

        // Prologue: fill stages 0..2
        #pragma unroll
        for (int st = 0; st < NSTAGE - 1; st++) {
            uint32_t s = sb + st * STAGE_B;
            fill_tile(s + 0 * TILE_B, aH, st * BK, tid);
            fill_tile(s + 1 * TILE_B, aL, st * BK, tid);
            fill_tile(s + 2 * TILE_B, bW, st * BK, tid);
            CP_COMMIT();
        }

        int stage = 0;
        for (int it = 0; it < NIT; it++) {
            uint32_t s = sb + stage * STAGE_B;
            CP_WAIT2();
            __syncthreads();

            const uint32_t sAh = s + 0 * TILE_B;
            const uint32_t sAl = s + 1 * TILE_B;
            const uint32_t sBw = s + 2 * TILE_B;

            #pragma unroll
            for (int ks = 0; ks < 2; ks++) {
                uint32_t fAh[2][4], fAl[2][4];
                #pragma unroll
                for (int mt = 0; mt < 2; mt++) {
                    int row = wm * 32 + mt * 16 + a_row_off;
                    uint32_t ad = swz(row, ks * 2 + a_half);
                    ldsm_x4(fAh[mt][0], fAh[mt][1], fAh[mt][2], fAh[mt][3], sAh + ad);
                    ldsm_x4(fAl[mt][0], fAl[mt][1], fAl[mt][2], fAl[mt][3], sAl + ad);
                }
                #pragma unroll
                for (int g = 0; g < 4; g++) {
                    int row = wn * 64 + g * 16 + b_row_off;
                    uint32_t bd = swz(row, ks * 2 + b_half);
                    uint32_t b0, b1, b2, b3;
                    ldsm_x4(b0, b1, b2, b3, sBw + bd);
                    #pragma unroll
                    for (int mt = 0; mt < 2; mt++) {
                        mma_f16(acc[mt][g * 2 + 0], fAh[mt], b0, b1);
                        mma_f16(acc[mt][g * 2 + 1], fAh[mt], b2, b3);
                        mma_f16(acc[mt][g * 2 + 0], fAl[mt], b0, b1);
                        mma_f16(acc[mt][g * 2 + 1], fAl[mt], b2, b3);
                    }
                }
            }

            if (it + NSTAGE - 1 < NIT) {
                int fs = stage + NSTAGE - 1;
                if (fs >= NSTAGE) fs -= NSTAGE;
                uint32_t f = sb + fs * STAGE_B;
                int k0 = (it + NSTAGE - 1) * BK;
                fill_tile(f + 0 * TILE_B, aH, k0, tid);
                fill_tile(f + 1 * TILE_B, aL, k0, tid);
                fill_tile(f + 2 * TILE_B, bW, k0, tid);
            }
            CP_COMMIT();
            stage = stage + 1 >= NSTAGE ? 0 : stage + 1;
        }

        // Epilogue
        #pragma unroll
        for (int mt = 0; mt < 2; mt++) {
            #pragma unroll
            for (int nt = 0; nt < 8; nt++) {
                int r   = m0 + wm * 32 + mt * 16 + gid;
                int col = n0 + wn * 64 + nt * 8 + tig * 2;
                if (MODE == 0) {
                    #pragma unroll
                    for (int half = 0; half < 2; half++) {
                        int rr = r + half * 8;
                        __half h0, l0, h1, l1;
                        f16split(acc[mt][nt][half * 2 + 0], h0, l0);
                        f16split(acc[mt][nt][half * 2 + 1], h1, l1);
                        size_t a = (size_t)rr * GN + col;
                        *(__half2*)(g_q_hi + a) = __half2(h0, h1);
                        *(__half2*)(g_q_lo + a) = __half2(l0, l1);
                    }
                } else {
                    float b0v = bias[col], b1v = bias[col + 1];
                    float2 v0 = make_float2(acc[mt][nt][0] + b0v, acc[mt][nt][1] + b1v);
                    float2 v1 = make_float2(acc[mt][nt][2] + b0v, acc[mt][nt][3] + b1v);
                    *(float2*)(Cp + (size_t)r * GN + col)       = v0;
                    *(float2*)(Cp + (size_t)(r + 8) * GN + col) = v1;
                }
            }
        }
    }
}

// ---------------------------------------------------------------------------
// HMMA flash attention (fp16x2). CTA = 128 queries x one (b,h). 8 warps.
// R12: occupancy 3 CTAs/SM (smem 3x62.5KB fits; ~90 live regs).
// ---------------------------------------------------------------------------
#define ASM_Q   0
#define ASM_K   (2 * 128 * 128)                 // 32768
#define ASM_V   (ASM_K + LPAD * 128)            // 32768 + 14336 = 47104
#define ASM_TOT (ASM_V + 64 * 240)              // 47104 + 15360 = 62464

__device__ __forceinline__ uint32_t swz128(int row, int chunk) {
    return (uint32_t)(row * 128 + ((chunk ^ (row & 7)) << 4));
}

__global__ void __launch_bounds__(256, 3) attn_kernel()
{
    extern __shared__ char asmem[];
    const uint32_t sb = smem_to_u32(asmem);
    const uint32_t sQh = sb + ASM_Q,  sQl = sQh + 128 * 128;
    const uint32_t sK  = sb + ASM_K;
    const uint32_t sV  = sb + ASM_V;

    const int tid  = threadIdx.x;
    const int wid  = tid >> 5;
    const int lane = tid & 31;
    const int bh = blockIdx.y;
    const int batch = bh / NHEADS;
    const int h = bh % NHEADS;
    const int qrow0 = batch * S_ + blockIdx.x * 128;

    // ---- loads (one-shot, cp.async) ----
    {
        const __half* qh = g_q_hi + (size_t)qrow0 * H_ + h * DH;
        const __half* ql = g_q_lo + (size_t)qrow0 * H_ + h * DH;
        #pragma unroll
        for (int i = 0; i < 4; i++) {
            int idx = i * 256 + tid;            // 0..1023
            int row = idx >> 3, c = idx & 7;
            CP_ASYNC_16(sQh + swz128(row, c), qh + (size_t)row * H_ + c * 8);
            CP_ASYNC_16(sQl + swz128(row, c), ql + (size_t)row * H_ + c * 8);
        }
        const __half* kp = g_k + (size_t)batch * LPAD * H_ + h * DH;
        for (int idx = tid; idx < LPAD * 8; idx += 256) {
            int row = idx >> 3, c = idx & 7;
            CP_ASYNC_16(sK + swz128(row, c), kp + (size_t)row * H_ + c * 8);
        }
        const __half* vp = g_vt + ((size_t)batch * H_ + h * DH) * LPAD2;
        for (int idx = tid; idx < 64 * 14; idx += 256) {
            int row = idx / 14, c = idx % 14;
            CP_ASYNC_16(sV + (uint32_t)(row * 240 + c * 16),
                        vp + (size_t)row * LPAD2 + c * 8);
        }
        CP_COMMIT();
    }
    CP_WAIT0();
    __syncthreads();

    const int gid = lane >> 2, tig = lane & 3;
    const int a_row_off = (lane & 7) + ((lane >> 3) & 1) * 8;
    const int a_half    = lane >> 4;
    const int b_row_off = (lane & 7) + ((lane >> 4) & 1) * 8;
    const int b_half    = (lane >> 3) & 1;

    // q fragments (held across the l-loop): 4 k-steps x hi/lo
    uint32_t fQh[4][4], fQl[4][4];
    #pragma unroll
    for (int ks = 0; ks < 4; ks++) {
        int row = wid * 16 + a_row_off;
        uint32_t ad = swz128(row, ks * 2 + a_half);
        ldsm_x4(fQh[ks][0], fQh[ks][1], fQh[ks][2], fQh[ks][3], sQh + ad);
        ldsm_x4(fQl[ks][0], fQl[ks][1], fQl[ks][2], fQl[ks][3], sQl + ad);
    }

    float acc[8][4];
    #pragma unroll
    for (int nt = 0; nt < 8; nt++)
        #pragma unroll
        for (int c = 0; c < 4; c++) acc[nt][c] = 0.f;
    float rs0 = 0.f, rs1 = 0.f;
    const float scale = 0.125f;

    #pragma unroll
    for (int kt = 0; kt < 7; kt++) {       // l tiles of 16 (0..111)
        // --- QK scores for n-tiles 2kt, 2kt+1 ---
        float c0[4] = {0.f, 0.f, 0.f, 0.f};
        float c1[4] = {0.f, 0.f, 0.f, 0.f};
        #pragma unroll
        for (int ks = 0; ks < 4; ks++) {
            int row = kt * 16 + b_row_off;
            uint32_t bd = swz128(row, ks * 2 + b_half);
            uint32_t kb0, kb1, kb2, kb3;
            ldsm_x4(kb0, kb1, kb2, kb3, sK + bd);
            mma_f16(c0, fQh[ks], kb0, kb1);
            mma_f16(c1, fQh[ks], kb2, kb3);
            mma_f16(c0, fQl[ks], kb0, kb1);
            mma_f16(c1, fQl[ks], kb2, kb3);
        }
        // --- exp + mask + row sums ---
        float e0[4], e1[4];
        #pragma unroll
        for (int j = 0; j < 4; j++) {
            e0[j] = __expf(c0[j] * scale);
            e1[j] = __expf(c1[j] * scale);
        }
        if (kt == 6) {   // n-tile 13: cols 104..111, mask col >= 109
            float m0v = (104 + 2 * tig <= 108) ? 1.f : 0.f;
            float m1v = (105 + 2 * tig <= 108) ? 1.f : 0.f;
            e1[0] *= m0v; e1[1] *= m1v; e1[2] *= m0v; e1[3] *= m1v;
        }
        rs0 += e0[0] + e0[1] + e1[0] + e1[1];
        rs1 += e0[2] + e0[3] + e1[2] + e1[3];
        // --- p fragments (FA2 C->A repack) + fp16 lo split ---
        uint32_t ah[4], al[4];
        float ev[8] = {e0[0], e0[1], e0[2], e0[3], e1[0], e1[1], e1[2], e1[3]};
        #pragma unroll
        for (int j = 0; j < 4; j++) {
            __half2 hh = __floats2half2_rn(ev[2 * j], ev[2 * j + 1]);
            ah[j] = h2_bits(hh);
            __half2 ll = __floats2half2_rn(ev[2 * j]     - __half2float(hh.x),
                                           ev[2 * j + 1] - __half2float(hh.y));
            al[j] = h2_bits(ll);
        }
        // --- PV: acc += p @ V^T-tile (k16 = these 16 l's) ---
        #pragma unroll
        for (int g = 0; g < 4; g++) {
            uint32_t bd = (uint32_t)((g * 16 + b_row_off) * 240 +
                                     (kt * 2 + b_half) * 16);
            uint32_t vb0, vb1, vb2, vb3;
            ldsm_x4(vb0, vb1, vb2, vb3, sV + bd);
            mma_f16(acc[g * 2 + 0], ah, vb0, vb1);
            mma_f16(acc[g * 2 + 1], ah, vb2, vb3);
            mma_f16(acc[g * 2 + 0], al, vb0, vb1);
            mma_f16(acc[g * 2 + 1], al, vb2, vb3);
        }
    }

    // quad reduction of row sums
    rs0 += __shfl_xor_sync(0xffffffffu, rs0, 1);
    rs0 += __shfl_xor_sync(0xffffffffu, rs0, 2);
    rs1 += __shfl_xor_sync(0xffffffffu, rs1, 1);
    rs1 += __shfl_xor_sync(0xffffffffu, rs1, 2);
    const float inv0 = 1.f / rs0;
    const float inv1 = 1.f / rs1;

    // epilogue: normalize, split, store to g_att_hi/lo
    const int r0 = qrow0 + wid * 16 + gid;
    #pragma unroll
    for (int nt = 0; nt < 8; nt++) {
        int col = h * DH + nt * 8 + tig * 2;
        __half h0, l0, h1, l1;
        f16split(acc[nt][0] * inv0, h0, l0);
        f16split(acc[nt][1] * inv0, h1, l1);
        size_t a = (size_t)r0 * H_ + col;
        *(__half2*)(g_att_hi + a) = __half2(h0, h1);
        *(__half2*)(g_att_lo + a) = __half2(l0, l1);
        f16split(acc[nt][2] * inv1, h0, l0);
        f16split(acc[nt][3] * inv1, h1, l1);
        a = (size_t)(r0 + 8) * H_ + col;
        *(__half2*)(g_att_hi + a) = __half2(h0, h1);
        *(__half2*)(g_att_lo + a) = __half2(l0, l1);
    }
}

// ---------------------------------------------------------------------------
// Side streams + events for fork/join inside graph capture (host objects).
// ---------------------------------------------------------------------------
struct SideStreams {
    cudaStream_t s1, s2;
    cudaEvent_t ef1, ef2, e_kv, e_w;
    SideStreams() {
        cudaStreamCreateWithFlags(&s1, cudaStreamNonBlocking);
        cudaStreamCreateWithFlags(&s2, cudaStreamNonBlocking);
        cudaEventCreateWithFlags(&ef1, cudaEventDisableTiming);
        cudaEventCreateWithFlags(&ef2, cudaEventDisableTiming);
        cudaEventCreateWithFlags(&e_kv, cudaEventDisableTiming);
        cudaEventCreateWithFlags(&e_w, cudaEventDisableTiming);
    }
};
static SideStreams& side() { static SideStreams s; return s; }

// ---------------------------------------------------------------------------
extern "C" void kernel_launch(void* const* d_in, const int* in_sizes, int n_in,
                              void* d_out, int out_size)
{
    (void)in_sizes; (void)n_in; (void)out_size;
    const float* hs    = (const float*)d_in[0];
    const float* ehs   = (const float*)d_in[1];
    const float* idemb = (const float*)d_in[2];
    const float* Wq    = (const float*)d_in[3];
    const float* Wk    = (const float*)d_in[4];
    const float* Wv    = (const float*)d_in[5];
    const float* Wid_k = (const float*)d_in[6];
    const float* Wid_v = (const float*)d_in[7];
    const float* Wout  = (const float*)d_in[8];
    const float* bout  = (const float*)d_in[9];
    float* out = (float*)d_out;

    const int attn_smem = ASM_TOT;            // 62,464 B
    const int gemm_smem = NSTAGE * STAGE_B;   // 98,304 B
    cudaFuncSetAttribute(attn_kernel,
                         cudaFuncAttributeMaxDynamicSharedMemorySize, attn_smem);
    cudaFuncSetAttribute(gemm_hmma<0>,
                         cudaFuncAttributeMaxDynamicSharedMemorySize, gemm_smem);
    cudaFuncSetAttribute(gemm_hmma<1>,
                         cudaFuncAttributeMaxDynamicSharedMemorySize, gemm_smem);

    SideStreams& ss = side();

    // Fork: kv on s1, weight transpose on s2, concurrent with critical path.
    cudaEventRecord(ss.ef1, 0);
    cudaStreamWaitEvent(ss.s1, ss.ef1, 0);
    cudaEventRecord(ss.ef2, 0);
    cudaStreamWaitEvent(ss.s2, ss.ef2, 0);

    kv_kernel<<<dim3(H_ / 64, (B_ * T_ + 63) / 64, 4), 256, 0, ss.s1>>>(
        ehs, idemb, Wk, Wv, Wid_k, Wid_v);
    cudaEventRecord(ss.e_kv, ss.s1);

    tsplit_kernel<<<dim3(H_ / 32, H_ / 32, 2), dim3(32, 8), 0, ss.s2>>>(Wq, Wout);
    cudaEventRecord(ss.e_w, ss.s2);

    // Main stream: hidden_states split (also resets gemm tile counters)
    split_kernel<<<(ROWS * H_ / 4 + 255) / 256, 256>>>(hs);

    // gemm0 needs g_wq (join s2)
    cudaStreamWaitEvent(0, ss.e_w, 0);
    gemm_hmma<0><<<GEMM_CTAS, 256, gemm_smem>>>(nullptr, nullptr);

    // attention needs K/V (join s1)
    cudaStreamWaitEvent(0, ss.e_kv, 0);
    attn_kernel<<<dim3(S_ / 128, B_ * NHEADS), 256, attn_smem>>>();

    // out = att @ Wout + bout
    gemm_hmma<1><<<GEMM_CTAS, 256, gemm_smem>>>(bout, out);
}

// round 13
// speedup vs baseline: 1.1489x; 1.1489x over previous
#include <cuda_runtime.h>
#include <cuda_fp16.h>
#include <cstdint>
#include <math.h>

// Problem constants
#define B_      4
#define S_      4096
#define H_      1280
#define C_      2048
#define T_      77
#define I_      32
#define NHEADS  20
#define DH      64
#define L_      (T_ + I_)       // 109
#define LPAD    112             // K rows padded (mult of 16)
#define LPAD2   120             // V^T row length (240B rows -> conflict-free)
#define ROWS    (B_ * S_)       // 16384

// ---------------------------------------------------------------------------
// Scratch (device globals; zero-initialized; no allocations allowed)
// fp16 2-product scheme: activations split hi/lo, weights/K/V single fp16.
// ---------------------------------------------------------------------------
__device__ __half g_q_hi[ROWS * H_];
__device__ __half g_q_lo[ROWS * H_];
__device__ __half g_att_hi[ROWS * H_];
__device__ __half g_att_lo[ROWS * H_];
__device__ __half g_hs_hi[ROWS * H_];
__device__ __half g_hs_lo[ROWS * H_];
__device__ __half g_wq[H_ * H_];          // Wq^T [N,K]
__device__ __half g_wo[H_ * H_];          // Wout^T [N,K]
__device__ __half g_k[B_ * LPAD * H_];    // K [b][l][n], rows 109..111 zero
__device__ __half g_vt[B_ * H_ * LPAD2];  // V^T [b][n][l], l 109..119 zero

// ---------------------------------------------------------------------------
// PTX helpers (sm_100 base target — NO tcgen05, which needs the 'a' variant)
// ---------------------------------------------------------------------------
#define CP_ASYNC_16(dst, src) \
    asm volatile("cp.async.cg.shared.global [%0], [%1], 16;" :: "r"(dst), "l"(src) : "memory")
#define CP_COMMIT() asm volatile("cp.async.commit_group;" ::: "memory")
#define CP_WAIT2()  asm volatile("cp.async.wait_group 2;" ::: "memory")
#define CP_WAIT1()  asm volatile("cp.async.wait_group 1;" ::: "memory")
#define CP_WAIT0()  asm volatile("cp.async.wait_group 0;" ::: "memory")

__device__ __forceinline__ uint32_t smem_to_u32(const void* p) {
    uint32_t a;
    asm("{ .reg .u64 t; cvta.to.shared.u64 t, %1; cvt.u32.u64 %0, t; }"
        : "=r"(a) : "l"(p));
    return a;
}

__device__ __forceinline__ void ldsm_x4(uint32_t& r0, uint32_t& r1,
                                        uint32_t& r2, uint32_t& r3, uint32_t addr) {
    asm volatile("ldmatrix.sync.aligned.m8n8.x4.shared.b16 {%0,%1,%2,%3}, [%4];"
                 : "=r"(r0), "=r"(r1), "=r"(r2), "=r"(r3) : "r"(addr));
}

__device__ __forceinline__ void mma_f16(float* d, const uint32_t* a,
                                        uint32_t b0, uint32_t b1) {
    asm volatile(
        "mma.sync.aligned.m16n8k16.row.col.f32.f16.f16.f32 "
        "{%0,%1,%2,%3}, {%4,%5,%6,%7}, {%8,%9}, {%0,%1,%2,%3};"
        : "+f"(d[0]), "+f"(d[1]), "+f"(d[2]), "+f"(d[3])
        : "r"(a[0]), "r"(a[1]), "r"(a[2]), "r"(a[3]), "r"(b0), "r"(b1));
}

__device__ __forceinline__ uint32_t h2_bits(__half2 v) {
    return *reinterpret_cast<uint32_t*>(&v);
}

// fp16 two-term split of fp32 (exact to ~2^-22)
__device__ __forceinline__ void f16split(float x, __half& h, __half& l) {
    h = __float2half_rn(x);
    l = __float2half_rn(x - __half2float(h));
}

// ---------------------------------------------------------------------------
// Prep 1: elementwise split of hidden_states -> g_hs_hi/lo
// ---------------------------------------------------------------------------
__global__ void __launch_bounds__(256) split_kernel(const float* __restrict__ src)
{
    size_t i = ((size_t)blockIdx.x * 256 + threadIdx.x) * 4;
    float4 v = *(const float4*)(src + i);
    __half h0, l0, h1, l1, h2, l2, h3, l3;
    f16split(v.x, h0, l0); f16split(v.y, h1, l1);
    f16split(v.z, h2, l2); f16split(v.w, h3, l3);
    *(__half2*)(g_hs_hi + i)     = __half2(h0, h1);
    *(__half2*)(g_hs_hi + i + 2) = __half2(h2, h3);
    *(__half2*)(g_hs_lo + i)     = __half2(l0, l1);
    *(__half2*)(g_hs_lo + i + 2) = __half2(l2, l3);
}

// ---------------------------------------------------------------------------
// Prep 2: transpose Wq and Wout -> [N, K] single fp16
// ---------------------------------------------------------------------------
__global__ void __launch_bounds__(256) tsplit_kernel(const float* __restrict__ Wq,
                                                     const float* __restrict__ Wout)
{
    __shared__ float t[32][33];
    const float* W = blockIdx.z ? Wout : Wq;
    __half* dh = blockIdx.z ? g_wo : g_wq;
    int bx = blockIdx.x * 32, by = blockIdx.y * 32;
    int tx = threadIdx.x, ty = threadIdx.y;
    #pragma unroll
    for (int i = 0; i < 4; i++)
        t[ty + 8 * i][tx] = W[(size_t)(by + ty + 8 * i) * H_ + bx + tx];
    __syncthreads();
    #pragma unroll
    for (int i = 0; i < 4; i++) {
        size_t o = (size_t)(bx + ty + 8 * i) * H_ + by + tx;   // [n][k]
        dh[o] = __float2half_rn(t[tx][ty + 8 * i]);
    }
}

// ---------------------------------------------------------------------------
// KV build: fp32 SIMT GEMM; K -> [b][LPAD][H_] fp16, V -> V^T [b][H_][LPAD2].
// ---------------------------------------------------------------------------
__device__ __forceinline__ void kv_store(bool is_v, int b, int l, int n,
                                         const float* vals)
{
    if (!is_v) {
        size_t a = ((size_t)b * LPAD + l) * H_ + n;
        *(__half2*)(g_k + a)     = __half2(__float2half_rn(vals[0]), __float2half_rn(vals[1]));
        *(__half2*)(g_k + a + 2) = __half2(__float2half_rn(vals[2]), __float2half_rn(vals[3]));
    } else {
        #pragma unroll
        for (int j = 0; j < 4; j++)
            g_vt[((size_t)b * H_ + n + j) * LPAD2 + l] = __float2half_rn(vals[j]);
    }
}

__global__ void __launch_bounds__(256) kv_kernel(
    const float* __restrict__ ehs, const float* __restrict__ idemb,
    const float* __restrict__ Wk, const float* __restrict__ Wv,
    const float* __restrict__ Wid_k, const float* __restrict__ Wid_v)
{
    const int z = blockIdx.z;
    const bool is_id = (z >= 2);
    const bool is_v  = (z & 1);
    const float* A = is_id ? idemb : ehs;
    const float* W = is_id ? (is_v ? Wid_v : Wid_k) : (is_v ? Wv : Wk);
    const int Mloc = is_id ? (2 * I_) : (B_ * T_);

    const int m0 = blockIdx.y * 64;
    if (m0 >= Mloc) return;
    const int n0 = blockIdx.x * 64;

    __shared__ float As[16][68];
    __shared__ float Bs[16][64];

    const int tid  = threadIdx.x;
    const int arow = tid >> 2;
    const int ac4  = (tid & 3) * 4;
    const int brow = tid >> 4;
    const int bc4  = (tid & 15) * 4;
    const int tx   = tid & 15;
    const int ty   = tid >> 4;

    float acc[4][4];
    #pragma unroll
    for (int i = 0; i < 4; i++)
        #pragma unroll
        for (int j = 0; j < 4; j++) acc[i][j] = 0.f;

    for (int k0 = 0; k0 < C_; k0 += 16) {
        float4 av = make_float4(0.f, 0.f, 0.f, 0.f);
        if (m0 + arow < Mloc)
            av = *(const float4*)(A + (size_t)(m0 + arow) * C_ + k0 + ac4);
        float4 bv = *(const float4*)(W + (size_t)(k0 + brow) * H_ + n0 + bc4);
        __syncthreads();
        As[ac4 + 0][arow] = av.x;
        As[ac4 + 1][arow] = av.y;
        As[ac4 + 2][arow] = av.z;
        As[ac4 + 3][arow] = av.w;
        *(float4*)&Bs[brow][bc4] = bv;
        __syncthreads();
        #pragma unroll
        for (int kk = 0; kk < 16; kk++) {
            float4 a = *(const float4*)&As[kk][ty * 4];
            float4 b = *(const float4*)&Bs[kk][tx * 4];
            float am[4] = {a.x, a.y, a.z, a.w};
            float bn[4] = {b.x, b.y, b.z, b.w};
            #pragma unroll
            for (int i = 0; i < 4; i++)
                #pragma unroll
                for (int j = 0; j < 4; j++)
                    acc[i][j] += am[i] * bn[j];
        }
    }

    #pragma unroll
    for (int i = 0; i < 4; i++) {
        int r = m0 + ty * 4 + i;
        if (r >= Mloc) continue;
        if (!is_id) {
            int batch = r / T_, pos = r % T_;
            kv_store(is_v, batch, pos, n0 + tx * 4, acc[i]);
        } else {
            int hb = r >> 5, ii = r & 31;
            kv_store(is_v, hb,     T_ + ii, n0 + tx * 4, acc[i]);
            kv_store(is_v, hb + 2, T_ + ii, n0 + tx * 4, acc[i]);
        }
    }
}

// ---------------------------------------------------------------------------
// HMMA fp16x2 GEMM (R11 config — static grid, proven 284us / tensor 72.5%):
// CTA 128x128, BK=32, 8 warps (4x2), warp tile 32x64, 2 CTAs/SM, 4-stage
// cp.async (wait_group 2), R6 ordering (MMA first, refill after).
// MODE 0: A=g_hs B=g_wq -> fp16 splits to g_q_hi/lo
// MODE 1: A=g_att B=g_wo -> fp32 + bias to Cp
// ---------------------------------------------------------------------------
#define GK       H_          // 1280
#define GN       H_          // 1280
#define BK       32
#define NIT      (GK / BK)   // 40
#define TILE_B   (128 * 64)  // 8192 B
#define STAGE_B  (3 * TILE_B)   // Ah, Al, B = 24576 B
#define NSTAGE   4

__device__ __forceinline__ uint32_t swz(int row, int chunk) {
    return (uint32_t)(row * 64 + ((chunk ^ ((row >> 1) & 3)) << 4));
}

__device__ __forceinline__ void fill_tile(uint32_t dst, const __half* src,
                                          int k0, int tid)
{
    #pragma unroll
    for (int i = 0; i < 2; i++) {
        int idx = i * 256 + tid;
        int row = idx >> 2;
        int c   = idx & 3;
        CP_ASYNC_16(dst + swz(row, c),
                    src + (size_t)row * GK + k0 + c * 8);
    }
}

template<int MODE>
__global__ void __launch_bounds__(256, 2) gemm_hmma(
    const float* __restrict__ bias, float* __restrict__ Cp)
{
    const __half* Ahi = (MODE == 0) ? g_hs_hi : g_att_hi;
    const __half* Alo = (MODE == 0) ? g_hs_lo : g_att_lo;
    const __half* Bw  = (MODE == 0) ? g_wq : g_wo;

    extern __shared__ char smem[];
    const uint32_t sb = smem_to_u32(smem);

    const int tid  = threadIdx.x;
    const int wid  = tid >> 5;
    const int lane = tid & 31;
    const int wm   = wid >> 1;
    const int wn   = wid & 1;
    const int n0 = blockIdx.x * 128;
    const int m0 = blockIdx.y * 128;

    const __half* aH = Ahi + (size_t)m0 * GK;
    const __half* aL = Alo + (size_t)m0 * GK;
    const __half* bW = Bw  + (size_t)n0 * GK;

    const int a_row_off = (lane & 7) + ((lane >> 3) & 1) * 8;
    const int a_half    = lane >> 4;
    const int b_row_off = (lane & 7) + ((lane >> 4) & 1) * 8;
    const int b_half    = (lane >> 3) & 1;

    float acc[2][8][4];
    #pragma unroll
    for (int mt = 0; mt < 2; mt++)
        #pragma unroll
        for (int nt = 0; nt < 8; nt++)
            #pragma unroll
            for (int c = 0; c < 4; c++) acc[mt][nt][c] = 0.f;

    // Prologue: fill stages 0..2
    #pragma unroll
    for (int st = 0; st < NSTAGE - 1; st++) {
        uint32_t s = sb + st * STAGE_B;
        fill_tile(s + 0 * TILE_B, aH, st * BK, tid);
        fill_tile(s + 1 * TILE_B, aL, st * BK, tid);
        fill_tile(s + 2 * TILE_B, bW, st * BK, tid);
        CP_COMMIT();
    }

    int stage = 0;
    for (int it = 0; it < NIT; it++) {
        uint32_t s = sb + stage * STAGE_B;
        CP_WAIT2();
        __syncthreads();

        const uint32_t sAh = s + 0 * TILE_B;
        const uint32_t sAl = s + 1 * TILE_B;
        const uint32_t sBw = s + 2 * TILE_B;

        #pragma unroll
        for (int ks = 0; ks < 2; ks++) {
            uint32_t fAh[2][4], fAl[2][4];
            #pragma unroll
            for (int mt = 0; mt < 2; mt++) {
                int row = wm * 32 + mt * 16 + a_row_off;
                uint32_t ad = swz(row, ks * 2 + a_half);
                ldsm_x4(fAh[mt][0], fAh[mt][1], fAh[mt][2], fAh[mt][3], sAh + ad);
                ldsm_x4(fAl[mt][0], fAl[mt][1], fAl[mt][2], fAl[mt][3], sAl + ad);
            }
            #pragma unroll
            for (int g = 0; g < 4; g++) {
                int row = wn * 64 + g * 16 + b_row_off;
                uint32_t bd = swz(row, ks * 2 + b_half);
                uint32_t b0, b1, b2, b3;
                ldsm_x4(b0, b1, b2, b3, sBw + bd);
                #pragma unroll
                for (int mt = 0; mt < 2; mt++) {
                    mma_f16(acc[mt][g * 2 + 0], fAh[mt], b0, b1);
                    mma_f16(acc[mt][g * 2 + 1], fAh[mt], b2, b3);
                    mma_f16(acc[mt][g * 2 + 0], fAl[mt], b0, b1);
                    mma_f16(acc[mt][g * 2 + 1], fAl[mt], b2, b3);
                }
            }
        }

        if (it + NSTAGE - 1 < NIT) {
            int fs = stage + NSTAGE - 1;
            if (fs >= NSTAGE) fs -= NSTAGE;
            uint32_t f = sb + fs * STAGE_B;
            int k0 = (it + NSTAGE - 1) * BK;
            fill_tile(f + 0 * TILE_B, aH, k0, tid);
            fill_tile(f + 1 * TILE_B, aL, k0, tid);
            fill_tile(f + 2 * TILE_B, bW, k0, tid);
        }
        CP_COMMIT();
        stage = stage + 1 >= NSTAGE ? 0 : stage + 1;
    }

    // Epilogue
    const int gid = lane >> 2, tig = lane & 3;
    #pragma unroll
    for (int mt = 0; mt < 2; mt++) {
        #pragma unroll
        for (int nt = 0; nt < 8; nt++) {
            int r   = m0 + wm * 32 + mt * 16 + gid;
            int col = n0 + wn * 64 + nt * 8 + tig * 2;
            if (MODE == 0) {
                #pragma unroll
                for (int half = 0; half < 2; half++) {
                    int rr = r + half * 8;
                    __half h0, l0, h1, l1;
                    f16split(acc[mt][nt][half * 2 + 0], h0, l0);
                    f16split(acc[mt][nt][half * 2 + 1], h1, l1);
                    size_t a = (size_t)rr * GN + col;
                    *(__half2*)(g_q_hi + a) = __half2(h0, h1);
                    *(__half2*)(g_q_lo + a) = __half2(l0, l1);
                }
            } else {
                float b0v = bias[col], b1v = bias[col + 1];
                float2 v0 = make_float2(acc[mt][nt][0] + b0v, acc[mt][nt][1] + b1v);
                float2 v1 = make_float2(acc[mt][nt][2] + b0v, acc[mt][nt][3] + b1v);
                *(float2*)(Cp + (size_t)r * GN + col)       = v0;
                *(float2*)(Cp + (size_t)(r + 8) * GN + col) = v1;
            }
        }
    }
}

// ---------------------------------------------------------------------------
// HMMA flash attention (fp16x2). R13: CTA = 256 queries of one (b,h),
// processed as TWO sequential 128-row halves sharing ONE K/V smem load
// (halves attention's dominant L2 traffic). Q1 tile prefetched via a second
// cp.async group during half-0 compute. Per-half compute identical to R11.
// Smem: Q0 32KB | Q1 32KB | K 14KB | V 15KB = 95232 B (2 CTAs/SM).
// ---------------------------------------------------------------------------
#define ASM_Q0  0
#define ASM_Q1  (2 * 128 * 128)                 // 32768
#define ASM_K   (2 * ASM_Q1)                    // 65536
#define ASM_V   (ASM_K + LPAD * 128)            // 65536 + 14336 = 79872
#define ASM_TOT (ASM_V + 64 * 240)              // 79872 + 15360 = 95232

__device__ __forceinline__ uint32_t swz128(int row, int chunk) {
    return (uint32_t)(row * 128 + ((chunk ^ (row & 7)) << 4));
}

__global__ void __launch_bounds__(256, 2) attn_kernel()
{
    extern __shared__ char asmem[];
    const uint32_t sb = smem_to_u32(asmem);
    const uint32_t sK  = sb + ASM_K;
    const uint32_t sV  = sb + ASM_V;

    const int tid  = threadIdx.x;
    const int wid  = tid >> 5;
    const int lane = tid & 31;
    const int bh = blockIdx.y;
    const int batch = bh / NHEADS;
    const int h = bh % NHEADS;
    const int qrow0 = batch * S_ + blockIdx.x * 256;

    // ---- loads: group A = Q0 + K + V; group B = Q1 (prefetch) ----
    {
        const __half* qh = g_q_hi + (size_t)qrow0 * H_ + h * DH;
        const __half* ql = g_q_lo + (size_t)qrow0 * H_ + h * DH;
        const uint32_t sQ0h = sb + ASM_Q0, sQ0l = sQ0h + 128 * 128;
        #pragma unroll
        for (int i = 0; i < 4; i++) {
            int idx = i * 256 + tid;            // 0..1023
            int row = idx >> 3, c = idx & 7;
            CP_ASYNC_16(sQ0h + swz128(row, c), qh + (size_t)row * H_ + c * 8);
            CP_ASYNC_16(sQ0l + swz128(row, c), ql + (size_t)row * H_ + c * 8);
        }
        const __half* kp = g_k + (size_t)batch * LPAD * H_ + h * DH;
        for (int idx = tid; idx < LPAD * 8; idx += 256) {
            int row = idx >> 3, c = idx & 7;
            CP_ASYNC_16(sK + swz128(row, c), kp + (size_t)row * H_ + c * 8);
        }
        const __half* vp = g_vt + ((size_t)batch * H_ + h * DH) * LPAD2;
        for (int idx = tid; idx < 64 * 14; idx += 256) {
            int row = idx / 14, c = idx % 14;
            CP_ASYNC_16(sV + (uint32_t)(row * 240 + c * 16),
                        vp + (size_t)row * LPAD2 + c * 8);
        }
        CP_COMMIT();   // group A

        const uint32_t sQ1h = sb + ASM_Q1, sQ1l = sQ1h + 128 * 128;
        const __half* qh1 = qh + (size_t)128 * H_;
        const __half* ql1 = ql + (size_t)128 * H_;
        #pragma unroll
        for (int i = 0; i < 4; i++) {
            int idx = i * 256 + tid;
            int row = idx >> 3, c = idx & 7;
            CP_ASYNC_16(sQ1h + swz128(row, c), qh1 + (size_t)row * H_ + c * 8);
            CP_ASYNC_16(sQ1l + swz128(row, c), ql1 + (size_t)row * H_ + c * 8);
        }
        CP_COMMIT();   // group B
    }
    CP_WAIT1();        // group A (Q0+K+V) complete; Q1 still in flight
    __syncthreads();

    const int gid = lane >> 2, tig = lane & 3;
    const int a_row_off = (lane & 7) + ((lane >> 3) & 1) * 8;
    const int a_half    = lane >> 4;
    const int b_row_off = (lane & 7) + ((lane >> 4) & 1) * 8;
    const int b_half    = (lane >> 3) & 1;
    const float scale = 0.125f;

    for (int qh2 = 0; qh2 < 2; qh2++) {
        if (qh2 == 1) {
            CP_WAIT0();        // Q1 landed (overlapped with half-0 compute)
            __syncthreads();
        }
        const uint32_t sQh = sb + (qh2 ? ASM_Q1 : ASM_Q0);
        const uint32_t sQl = sQh + 128 * 128;

        // q fragments: 4 k-steps x hi/lo
        uint32_t fQh[4][4], fQl[4][4];
        #pragma unroll
        for (int ks = 0; ks < 4; ks++) {
            int row = wid * 16 + a_row_off;
            uint32_t ad = swz128(row, ks * 2 + a_half);
            ldsm_x4(fQh[ks][0], fQh[ks][1], fQh[ks][2], fQh[ks][3], sQh + ad);
            ldsm_x4(fQl[ks][0], fQl[ks][1], fQl[ks][2], fQl[ks][3], sQl + ad);
        }

        float acc[8][4];
        #pragma unroll
        for (int nt = 0; nt < 8; nt++)
            #pragma unroll
            for (int c = 0; c < 4; c++) acc[nt][c] = 0.f;
        float rs0 = 0.f, rs1 = 0.f;

        #pragma unroll
        for (int kt = 0; kt < 7; kt++) {       // l tiles of 16 (0..111)
            float c0[4] = {0.f, 0.f, 0.f, 0.f};
            float c1[4] = {0.f, 0.f, 0.f, 0.f};
            #pragma unroll
            for (int ks = 0; ks < 4; ks++) {
                int row = kt * 16 + b_row_off;
                uint32_t bd = swz128(row, ks * 2 + b_half);
                uint32_t kb0, kb1, kb2, kb3;
                ldsm_x4(kb0, kb1, kb2, kb3, sK + bd);
                mma_f16(c0, fQh[ks], kb0, kb1);
                mma_f16(c1, fQh[ks], kb2, kb3);
                mma_f16(c0, fQl[ks], kb0, kb1);
                mma_f16(c1, fQl[ks], kb2, kb3);
            }
            float e0[4], e1[4];
            #pragma unroll
            for (int j = 0; j < 4; j++) {
                e0[j] = __expf(c0[j] * scale);
                e1[j] = __expf(c1[j] * scale);
            }
            if (kt == 6) {   // n-tile 13: cols 104..111, mask col >= 109
                float m0v = (104 + 2 * tig <= 108) ? 1.f : 0.f;
                float m1v = (105 + 2 * tig <= 108) ? 1.f : 0.f;
                e1[0] *= m0v; e1[1] *= m1v; e1[2] *= m0v; e1[3] *= m1v;
            }
            rs0 += e0[0] + e0[1] + e1[0] + e1[1];
            rs1 += e0[2] + e0[3] + e1[2] + e1[3];

            uint32_t ah[4], al[4];
            float ev[8] = {e0[0], e0[1], e0[2], e0[3], e1[0], e1[1], e1[2], e1[3]};
            #pragma unroll
            for (int j = 0; j < 4; j++) {
                __half2 hh = __floats2half2_rn(ev[2 * j], ev[2 * j + 1]);
                ah[j] = h2_bits(hh);
                __half2 ll = __floats2half2_rn(ev[2 * j]     - __half2float(hh.x),
                                               ev[2 * j + 1] - __half2float(hh.y));
                al[j] = h2_bits(ll);
            }
            #pragma unroll
            for (int g = 0; g < 4; g++) {
                uint32_t bd = (uint32_t)((g * 16 + b_row_off) * 240 +
                                         (kt * 2 + b_half) * 16);
                uint32_t vb0, vb1, vb2, vb3;
                ldsm_x4(vb0, vb1, vb2, vb3, sV + bd);
                mma_f16(acc[g * 2 + 0], ah, vb0, vb1);
                mma_f16(acc[g * 2 + 1], ah, vb2, vb3);
                mma_f16(acc[g * 2 + 0], al, vb0, vb1);
                mma_f16(acc[g * 2 + 1], al, vb2, vb3);
            }
        }

        rs0 += __shfl_xor_sync(0xffffffffu, rs0, 1);
        rs0 += __shfl_xor_sync(0xffffffffu, rs0, 2);
        rs1 += __shfl_xor_sync(0xffffffffu, rs1, 1);
        rs1 += __shfl_xor_sync(0xffffffffu, rs1, 2);
        const float inv0 = 1.f / rs0;
        const float inv1 = 1.f / rs1;

        const int r0 = qrow0 + qh2 * 128 + wid * 16 + gid;
        #pragma unroll
        for (int nt = 0; nt < 8; nt++) {
            int col = h * DH + nt * 8 + tig * 2;
            __half h0, l0, h1, l1;
            f16split(acc[nt][0] * inv0, h0, l0);
            f16split(acc[nt][1] * inv0, h1, l1);
            size_t a = (size_t)r0 * H_ + col;
            *(__half2*)(g_att_hi + a) = __half2(h0, h1);
            *(__half2*)(g_att_lo + a) = __half2(l0, l1);
            f16split(acc[nt][2] * inv1, h0, l0);
            f16split(acc[nt][3] * inv1, h1, l1);
            a = (size_t)(r0 + 8) * H_ + col;
            *(__half2*)(g_att_hi + a) = __half2(h0, h1);
            *(__half2*)(g_att_lo + a) = __half2(l0, l1);
        }
    }
}

// ---------------------------------------------------------------------------
// Side streams + events for fork/join inside graph capture (host objects).
// ---------------------------------------------------------------------------
struct SideStreams {
    cudaStream_t s1, s2;
    cudaEvent_t ef1, ef2, e_kv, e_w;
    SideStreams() {
        cudaStreamCreateWithFlags(&s1, cudaStreamNonBlocking);
        cudaStreamCreateWithFlags(&s2, cudaStreamNonBlocking);
        cudaEventCreateWithFlags(&ef1, cudaEventDisableTiming);
        cudaEventCreateWithFlags(&ef2, cudaEventDisableTiming);
        cudaEventCreateWithFlags(&e_kv, cudaEventDisableTiming);
        cudaEventCreateWithFlags(&e_w, cudaEventDisableTiming);
    }
};
static SideStreams& side() { static SideStreams s; return s; }

// ---------------------------------------------------------------------------
extern "C" void kernel_launch(void* const* d_in, const int* in_sizes, int n_in,
                              void* d_out, int out_size)
{
    (void)in_sizes; (void)n_in; (void)out_size;
    const float* hs    = (const float*)d_in[0];
    const float* ehs   = (const float*)d_in[1];
    const float* idemb = (const float*)d_in[2];
    const float* Wq    = (const float*)d_in[3];
    const float* Wk    = (const float*)d_in[4];
    const float* Wv    = (const float*)d_in[5];
    const float* Wid_k = (const float*)d_in[6];
    const float* Wid_v = (const float*)d_in[7];
    const float* Wout  = (const float*)d_in[8];
    const float* bout  = (const float*)d_in[9];
    float* out = (float*)d_out;

    const int attn_smem = ASM_TOT;            // 95,232 B
    const int gemm_smem = NSTAGE * STAGE_B;   // 98,304 B
    cudaFuncSetAttribute(attn_kernel,
                         cudaFuncAttributeMaxDynamicSharedMemorySize, attn_smem);
    cudaFuncSetAttribute(gemm_hmma<0>,
                         cudaFuncAttributeMaxDynamicSharedMemorySize, gemm_smem);
    cudaFuncSetAttribute(gemm_hmma<1>,
                         cudaFuncAttributeMaxDynamicSharedMemorySize, gemm_smem);

    SideStreams& ss = side();

    // Fork: kv on s1, weight transpose on s2, concurrent with critical path.
    cudaEventRecord(ss.ef1, 0);
    cudaStreamWaitEvent(ss.s1, ss.ef1, 0);
    cudaEventRecord(ss.ef2, 0);
    cudaStreamWaitEvent(ss.s2, ss.ef2, 0);

    kv_kernel<<<dim3(H_ / 64, (B_ * T_ + 63) / 64, 4), 256, 0, ss.s1>>>(
        ehs, idemb, Wk, Wv, Wid_k, Wid_v);
    cudaEventRecord(ss.e_kv, ss.s1);

    tsplit_kernel<<<dim3(H_ / 32, H_ / 32, 2), dim3(32, 8), 0, ss.s2>>>(Wq, Wout);
    cudaEventRecord(ss.e_w, ss.s2);

    // Main stream: hidden_states split
    split_kernel<<<(ROWS * H_ / 4 + 255) / 256, 256>>>(hs);

    // gemm0 needs g_wq (join s2)
    cudaStreamWaitEvent(0, ss.e_w, 0);
    gemm_hmma<0><<<dim3(GN / 128, ROWS / 128), 256, gemm_smem>>>(nullptr, nullptr);

    // attention needs K/V (join s1)
    cudaStreamWaitEvent(0, ss.e_kv, 0);
    attn_kernel<<<dim3(S_ / 256, B_ * NHEADS), 256, attn_smem>>>();

    // out = att @ Wout + bout
    gemm_hmma<1><<<dim3(GN / 128, ROWS / 128), 256, gemm_smem>>>(bout, out);
}

// round 14
// speedup vs baseline: 1.1840x; 1.0306x over previous
#include <cuda_runtime.h>
#include <cuda_fp16.h>
#include <cstdint>
#include <math.h>

// Problem constants
#define B_      4
#define S_      4096
#define H_      1280
#define C_      2048
#define T_      77
#define I_      32
#define NHEADS  20
#define DH      64
#define L_      (T_ + I_)       // 109
#define LPAD    112             // K rows padded (mult of 16)
#define LPAD2   120             // V^T row length (240B rows -> conflict-free)
#define ROWS    (B_ * S_)       // 16384

// ---------------------------------------------------------------------------
// Scratch (device globals; zero-initialized; no allocations allowed)
// Precision plan: hs split (hi/lo) x wq single -> q split x K single (QK),
// p single x V single (PV), att single x wo split (hi/lo). 5 independent
// ~2^-12 rounding sources -> rel_err ~5e-4 (gate 1e-3).
// ---------------------------------------------------------------------------
__device__ __half g_q_hi[ROWS * H_];
__device__ __half g_q_lo[ROWS * H_];
__device__ __half g_att[ROWS * H_];       // attention out, single fp16
__device__ __half g_hs_hi[ROWS * H_];
__device__ __half g_hs_lo[ROWS * H_];
__device__ __half g_wq[H_ * H_];          // Wq^T [N,K], single fp16
__device__ __half g_wo_hi[H_ * H_];       // Wout^T [N,K], fp16 split
__device__ __half g_wo_lo[H_ * H_];
__device__ __half g_k[B_ * LPAD * H_];    // K [b][l][n], rows 109..111 zero
__device__ __half g_vt[B_ * H_ * LPAD2];  // V^T [b][n][l], l 109..119 zero

// ---------------------------------------------------------------------------
// PTX helpers (sm_100 base target — NO tcgen05, which needs the 'a' variant)
// ---------------------------------------------------------------------------
#define CP_ASYNC_16(dst, src) \
    asm volatile("cp.async.cg.shared.global [%0], [%1], 16;" :: "r"(dst), "l"(src) : "memory")
#define CP_COMMIT() asm volatile("cp.async.commit_group;" ::: "memory")
#define CP_WAIT2()  asm volatile("cp.async.wait_group 2;" ::: "memory")
#define CP_WAIT0()  asm volatile("cp.async.wait_group 0;" ::: "memory")

__device__ __forceinline__ uint32_t smem_to_u32(const void* p) {
    uint32_t a;
    asm("{ .reg .u64 t; cvta.to.shared.u64 t, %1; cvt.u32.u64 %0, t; }"
        : "=r"(a) : "l"(p));
    return a;
}

__device__ __forceinline__ void ldsm_x4(uint32_t& r0, uint32_t& r1,
                                        uint32_t& r2, uint32_t& r3, uint32_t addr) {
    asm volatile("ldmatrix.sync.aligned.m8n8.x4.shared.b16 {%0,%1,%2,%3}, [%4];"
                 : "=r"(r0), "=r"(r1), "=r"(r2), "=r"(r3) : "r"(addr));
}

__device__ __forceinline__ void mma_f16(float* d, const uint32_t* a,
                                        uint32_t b0, uint32_t b1) {
    asm volatile(
        "mma.sync.aligned.m16n8k16.row.col.f32.f16.f16.f32 "
        "{%0,%1,%2,%3}, {%4,%5,%6,%7}, {%8,%9}, {%0,%1,%2,%3};"
        : "+f"(d[0]), "+f"(d[1]), "+f"(d[2]), "+f"(d[3])
        : "r"(a[0]), "r"(a[1]), "r"(a[2]), "r"(a[3]), "r"(b0), "r"(b1));
}

__device__ __forceinline__ uint32_t h2_bits(__half2 v) {
    return *reinterpret_cast<uint32_t*>(&v);
}

// fp16 two-term split of fp32 (exact to ~2^-22)
__device__ __forceinline__ void f16split(float x, __half& h, __half& l) {
    h = __float2half_rn(x);
    l = __float2half_rn(x - __half2float(h));
}

// ---------------------------------------------------------------------------
// Prep 1: elementwise split of hidden_states -> g_hs_hi/lo
// ---------------------------------------------------------------------------
__global__ void __launch_bounds__(256) split_kernel(const float* __restrict__ src)
{
    size_t i = ((size_t)blockIdx.x * 256 + threadIdx.x) * 4;
    float4 v = *(const float4*)(src + i);
    __half h0, l0, h1, l1, h2, l2, h3, l3;
    f16split(v.x, h0, l0); f16split(v.y, h1, l1);
    f16split(v.z, h2, l2); f16split(v.w, h3, l3);
    *(__half2*)(g_hs_hi + i)     = __half2(h0, h1);
    *(__half2*)(g_hs_hi + i + 2) = __half2(h2, h3);
    *(__half2*)(g_hs_lo + i)     = __half2(l0, l1);
    *(__half2*)(g_hs_lo + i + 2) = __half2(l2, l3);
}

// ---------------------------------------------------------------------------
// Prep 2: transpose weights -> [N, K]. Wq: single fp16. Wout: fp16 hi/lo.
// ---------------------------------------------------------------------------
__global__ void __launch_bounds__(256) tsplit_kernel(const float* __restrict__ Wq,
                                                     const float* __restrict__ Wout)
{
    __shared__ float t[32][33];
    const bool is_wo = blockIdx.z != 0;
    const float* W = is_wo ? Wout : Wq;
    int bx = blockIdx.x * 32, by = blockIdx.y * 32;
    int tx = threadIdx.x, ty = threadIdx.y;
    #pragma unroll
    for (int i = 0; i < 4; i++)
        t[ty + 8 * i][tx] = W[(size_t)(by + ty + 8 * i) * H_ + bx + tx];
    __syncthreads();
    #pragma unroll
    for (int i = 0; i < 4; i++) {
        float v = t[tx][ty + 8 * i];
        size_t o = (size_t)(bx + ty + 8 * i) * H_ + by + tx;   // [n][k]
        if (!is_wo) {
            g_wq[o] = __float2half_rn(v);
        } else {
            __half h, l;
            f16split(v, h, l);
            g_wo_hi[o] = h;
            g_wo_lo[o] = l;
        }
    }
}

// ---------------------------------------------------------------------------
// KV build: fp32 SIMT GEMM; K -> [b][LPAD][H_] fp16, V -> V^T [b][H_][LPAD2].
// ---------------------------------------------------------------------------
__device__ __forceinline__ void kv_store(bool is_v, int b, int l, int n,
                                         const float* vals)
{
    if (!is_v) {
        size_t a = ((size_t)b * LPAD + l) * H_ + n;
        *(__half2*)(g_k + a)     = __half2(__float2half_rn(vals[0]), __float2half_rn(vals[1]));
        *(__half2*)(g_k + a + 2) = __half2(__float2half_rn(vals[2]), __float2half_rn(vals[3]));
    } else {
        #pragma unroll
        for (int j = 0; j < 4; j++)
            g_vt[((size_t)b * H_ + n + j) * LPAD2 + l] = __float2half_rn(vals[j]);
    }
}

__global__ void __launch_bounds__(256) kv_kernel(
    const float* __restrict__ ehs, const float* __restrict__ idemb,
    const float* __restrict__ Wk, const float* __restrict__ Wv,
    const float* __restrict__ Wid_k, const float* __restrict__ Wid_v)
{
    const int z = blockIdx.z;
    const bool is_id = (z >= 2);
    const bool is_v  = (z & 1);
    const float* A = is_id ? idemb : ehs;
    const float* W = is_id ? (is_v ? Wid_v : Wid_k) : (is_v ? Wv : Wk);
    const int Mloc = is_id ? (2 * I_) : (B_ * T_);

    const int m0 = blockIdx.y * 64;
    if (m0 >= Mloc) return;
    const int n0 = blockIdx.x * 64;

    __shared__ float As[16][68];
    __shared__ float Bs[16][64];

    const int tid  = threadIdx.x;
    const int arow = tid >> 2;
    const int ac4  = (tid & 3) * 4;
    const int brow = tid >> 4;
    const int bc4  = (tid & 15) * 4;
    const int tx   = tid & 15;
    const int ty   = tid >> 4;

    float acc[4][4];
    #pragma unroll
    for (int i = 0; i < 4; i++)
        #pragma unroll
        for (int j = 0; j < 4; j++) acc[i][j] = 0.f;

    for (int k0 = 0; k0 < C_; k0 += 16) {
        float4 av = make_float4(0.f, 0.f, 0.f, 0.f);
        if (m0 + arow < Mloc)
            av = *(const float4*)(A + (size_t)(m0 + arow) * C_ + k0 + ac4);
        float4 bv = *(const float4*)(W + (size_t)(k0 + brow) * H_ + n0 + bc4);
        __syncthreads();
        As[ac4 + 0][arow] = av.x;
        As[ac4 + 1][arow] = av.y;
        As[ac4 + 2][arow] = av.z;
        As[ac4 + 3][arow] = av.w;
        *(float4*)&Bs[brow][bc4] = bv;
        __syncthreads();
        #pragma unroll
        for (int kk = 0; kk < 16; kk++) {
            float4 a = *(const float4*)&As[kk][ty * 4];
            float4 b = *(const float4*)&Bs[kk][tx * 4];
            float am[4] = {a.x, a.y, a.z, a.w};
            float bn[4] = {b.x, b.y, b.z, b.w};
            #pragma unroll
            for (int i = 0; i < 4; i++)
                #pragma unroll
                for (int j = 0; j < 4; j++)
                    acc[i][j] += am[i] * bn[j];
        }
    }

    #pragma unroll
    for (int i = 0; i < 4; i++) {
        int r = m0 + ty * 4 + i;
        if (r >= Mloc) continue;
        if (!is_id) {
            int batch = r / T_, pos = r % T_;
            kv_store(is_v, batch, pos, n0 + tx * 4, acc[i]);
        } else {
            int hb = r >> 5, ii = r & 31;
            kv_store(is_v, hb,     T_ + ii, n0 + tx * 4, acc[i]);
            kv_store(is_v, hb + 2, T_ + ii, n0 + tx * 4, acc[i]);
        }
    }
}

// ---------------------------------------------------------------------------
// HMMA fp16x2 GEMM (R11 loop structure, proven 284us). CTA 128x128, BK=32,
// 8 warps (4x2), warp 32x64, 2 CTAs/SM, 4-stage cp.async (wait 2).
// MODE 0: A split (hs hi/lo) x B single (wq) -> q splits.
// MODE 1: A single (att)     x B split (wo hi/lo) -> fp32 + bias to Cp.
// Both: 3 smem tiles/stage, 2 MMA products per (g,mt).
// ---------------------------------------------------------------------------
#define GK       H_          // 1280
#define GN       H_          // 1280
#define BK       32
#define NIT      (GK / BK)   // 40
#define TILE_B   (128 * 64)  // 8192 B
#define STAGE_B  (3 * TILE_B)   // 24576 B
#define NSTAGE   4

__device__ __forceinline__ uint32_t swz(int row, int chunk) {
    return (uint32_t)(row * 64 + ((chunk ^ ((row >> 1) & 3)) << 4));
}

__device__ __forceinline__ void fill_tile(uint32_t dst, const __half* src,
                                          int k0, int tid)
{
    #pragma unroll
    for (int i = 0; i < 2; i++) {
        int idx = i * 256 + tid;
        int row = idx >> 2;
        int c   = idx & 3;
        CP_ASYNC_16(dst + swz(row, c),
                    src + (size_t)row * GK + k0 + c * 8);
    }
}

template<int MODE>
__global__ void __launch_bounds__(256, 2) gemm_hmma(
    const float* __restrict__ bias, float* __restrict__ Cp)
{
    // Tile roles per stage: T0/T1 = pair (split), T2 = single... arranged so
    // MODE 0: T0=Ahi T1=Alo T2=B;  MODE 1: T0=A T1=Bhi T2=Blo.
    const __half* p0 = (MODE == 0) ? g_hs_hi : g_att;
    const __half* p1 = (MODE == 0) ? g_hs_lo : g_wo_hi;
    const __half* p2 = (MODE == 0) ? g_wq    : g_wo_lo;

    extern __shared__ char smem[];
    const uint32_t sb = smem_to_u32(smem);

    const int tid  = threadIdx.x;
    const int wid  = tid >> 5;
    const int lane = tid & 31;
    const int wm   = wid >> 1;
    const int wn   = wid & 1;
    const int n0 = blockIdx.x * 128;
    const int m0 = blockIdx.y * 128;

    const __half* s0 = p0 + (size_t)m0 * GK;                      // A-side
    const __half* s1 = p1 + (size_t)((MODE == 0) ? m0 : n0) * GK;
    const __half* s2 = p2 + (size_t)n0 * GK;                      // B-side

    const int a_row_off = (lane & 7) + ((lane >> 3) & 1) * 8;
    const int a_half    = lane >> 4;
    const int b_row_off = (lane & 7) + ((lane >> 4) & 1) * 8;
    const int b_half    = (lane >> 3) & 1;

    float acc[2][8][4];
    #pragma unroll
    for (int mt = 0; mt < 2; mt++)
        #pragma unroll
        for (int nt = 0; nt < 8; nt++)
            #pragma unroll
            for (int c = 0; c < 4; c++) acc[mt][nt][c] = 0.f;

    #pragma unroll
    for (int st = 0; st < NSTAGE - 1; st++) {
        uint32_t s = sb + st * STAGE_B;
        fill_tile(s + 0 * TILE_B, s0, st * BK, tid);
        fill_tile(s + 1 * TILE_B, s1, st * BK, tid);
        fill_tile(s + 2 * TILE_B, s2, st * BK, tid);
        CP_COMMIT();
    }

    int stage = 0;
    for (int it = 0; it < NIT; it++) {
        uint32_t s = sb + stage * STAGE_B;
        CP_WAIT2();
        __syncthreads();

        const uint32_t sT0 = s + 0 * TILE_B;
        const uint32_t sT1 = s + 1 * TILE_B;
        const uint32_t sT2 = s + 2 * TILE_B;

        #pragma unroll
        for (int ks = 0; ks < 2; ks++) {
            if (MODE == 0) {
                // A split x B single
                uint32_t fAh[2][4], fAl[2][4];
                #pragma unroll
                for (int mt = 0; mt < 2; mt++) {
                    int row = wm * 32 + mt * 16 + a_row_off;
                    uint32_t ad = swz(row, ks * 2 + a_half);
                    ldsm_x4(fAh[mt][0], fAh[mt][1], fAh[mt][2], fAh[mt][3], sT0 + ad);
                    ldsm_x4(fAl[mt][0], fAl[mt][1], fAl[mt][2], fAl[mt][3], sT1 + ad);
                }
                #pragma unroll
                for (int g = 0; g < 4; g++) {
                    int row = wn * 64 + g * 16 + b_row_off;
                    uint32_t bd = swz(row, ks * 2 + b_half);
                    uint32_t b0, b1, b2, b3;
                    ldsm_x4(b0, b1, b2, b3, sT2 + bd);
                    #pragma unroll
                    for (int mt = 0; mt < 2; mt++) {
                        mma_f16(acc[mt][g * 2 + 0], fAh[mt], b0, b1);
                        mma_f16(acc[mt][g * 2 + 1], fAh[mt], b2, b3);
                        mma_f16(acc[mt][g * 2 + 0], fAl[mt], b0, b1);
                        mma_f16(acc[mt][g * 2 + 1], fAl[mt], b2, b3);
                    }
                }
            } else {
                // A single x B split
                uint32_t fA[2][4];
                #pragma unroll
                for (int mt = 0; mt < 2; mt++) {
                    int row = wm * 32 + mt * 16 + a_row_off;
                    uint32_t ad = swz(row, ks * 2 + a_half);
                    ldsm_x4(fA[mt][0], fA[mt][1], fA[mt][2], fA[mt][3], sT0 + ad);
                }
                #pragma unroll
                for (int g = 0; g < 4; g++) {
                    int row = wn * 64 + g * 16 + b_row_off;
                    uint32_t bd = swz(row, ks * 2 + b_half);
                    uint32_t h0, h1, h2, h3, l0, l1, l2, l3;
                    ldsm_x4(h0, h1, h2, h3, sT1 + bd);
                    ldsm_x4(l0, l1, l2, l3, sT2 + bd);
                    #pragma unroll
                    for (int mt = 0; mt < 2; mt++) {
                        mma_f16(acc[mt][g * 2 + 0], fA[mt], h0, h1);
                        mma_f16(acc[mt][g * 2 + 1], fA[mt], h2, h3);
                        mma_f16(acc[mt][g * 2 + 0], fA[mt], l0, l1);
                        mma_f16(acc[mt][g * 2 + 1], fA[mt], l2, l3);
                    }
                }
            }
        }

        if (it + NSTAGE - 1 < NIT) {
            int fs = stage + NSTAGE - 1;
            if (fs >= NSTAGE) fs -= NSTAGE;
            uint32_t f = sb + fs * STAGE_B;
            int k0 = (it + NSTAGE - 1) * BK;
            fill_tile(f + 0 * TILE_B, s0, k0, tid);
            fill_tile(f + 1 * TILE_B, s1, k0, tid);
            fill_tile(f + 2 * TILE_B, s2, k0, tid);
        }
        CP_COMMIT();
        stage = stage + 1 >= NSTAGE ? 0 : stage + 1;
    }

    // Epilogue
    const int gid = lane >> 2, tig = lane & 3;
    #pragma unroll
    for (int mt = 0; mt < 2; mt++) {
        #pragma unroll
        for (int nt = 0; nt < 8; nt++) {
            int r   = m0 + wm * 32 + mt * 16 + gid;
            int col = n0 + wn * 64 + nt * 8 + tig * 2;
            if (MODE == 0) {
                #pragma unroll
                for (int half = 0; half < 2; half++) {
                    int rr = r + half * 8;
                    __half h0, l0, h1, l1;
                    f16split(acc[mt][nt][half * 2 + 0], h0, l0);
                    f16split(acc[mt][nt][half * 2 + 1], h1, l1);
                    size_t a = (size_t)rr * GN + col;
                    *(__half2*)(g_q_hi + a) = __half2(h0, h1);
                    *(__half2*)(g_q_lo + a) = __half2(l0, l1);
                }
            } else {
                float b0v = bias[col], b1v = bias[col + 1];
                float2 v0 = make_float2(acc[mt][nt][0] + b0v, acc[mt][nt][1] + b1v);
                float2 v1 = make_float2(acc[mt][nt][2] + b0v, acc[mt][nt][3] + b1v);
                *(float2*)(Cp + (size_t)r * GN + col)       = v0;
                *(float2*)(Cp + (size_t)(r + 8) * GN + col) = v1;
            }
        }
    }
}

// ---------------------------------------------------------------------------
// HMMA flash attention (R11 shape: CTA = 128 queries x one (b,h), 2560 CTAs).
// R14: PV uses single-fp16 p (drops p_lo product: 32 vs 40 MMA/kt) and the
// epilogue writes single-fp16 g_att (no split, half the stores).
// ---------------------------------------------------------------------------
#define ASM_Q   0
#define ASM_K   (2 * 128 * 128)                 // 32768
#define ASM_V   (ASM_K + LPAD * 128)            // 47104
#define ASM_TOT (ASM_V + 64 * 240)              // 62464

__device__ __forceinline__ uint32_t swz128(int row, int chunk) {
    return (uint32_t)(row * 128 + ((chunk ^ (row & 7)) << 4));
}

__global__ void __launch_bounds__(256, 2) attn_kernel()
{
    extern __shared__ char asmem[];
    const uint32_t sb = smem_to_u32(asmem);
    const uint32_t sQh = sb + ASM_Q,  sQl = sQh + 128 * 128;
    const uint32_t sK  = sb + ASM_K;
    const uint32_t sV  = sb + ASM_V;

    const int tid  = threadIdx.x;
    const int wid  = tid >> 5;
    const int lane = tid & 31;
    const int bh = blockIdx.y;
    const int batch = bh / NHEADS;
    const int h = bh % NHEADS;
    const int qrow0 = batch * S_ + blockIdx.x * 128;

    // ---- loads (one-shot, cp.async) ----
    {
        const __half* qh = g_q_hi + (size_t)qrow0 * H_ + h * DH;
        const __half* ql = g_q_lo + (size_t)qrow0 * H_ + h * DH;
        #pragma unroll
        for (int i = 0; i < 4; i++) {
            int idx = i * 256 + tid;            // 0..1023
            int row = idx >> 3, c = idx & 7;
            CP_ASYNC_16(sQh + swz128(row, c), qh + (size_t)row * H_ + c * 8);
            CP_ASYNC_16(sQl + swz128(row, c), ql + (size_t)row * H_ + c * 8);
        }
        const __half* kp = g_k + (size_t)batch * LPAD * H_ + h * DH;
        for (int idx = tid; idx < LPAD * 8; idx += 256) {
            int row = idx >> 3, c = idx & 7;
            CP_ASYNC_16(sK + swz128(row, c), kp + (size_t)row * H_ + c * 8);
        }
        const __half* vp = g_vt + ((size_t)batch * H_ + h * DH) * LPAD2;
        for (int idx = tid; idx < 64 * 14; idx += 256) {
            int row = idx / 14, c = idx % 14;
            CP_ASYNC_16(sV + (uint32_t)(row * 240 + c * 16),
                        vp + (size_t)row * LPAD2 + c * 8);
        }
        CP_COMMIT();
    }
    CP_WAIT0();
    __syncthreads();

    const int gid = lane >> 2, tig = lane & 3;
    const int a_row_off = (lane & 7) + ((lane >> 3) & 1) * 8;
    const int a_half    = lane >> 4;
    const int b_row_off = (lane & 7) + ((lane >> 4) & 1) * 8;
    const int b_half    = (lane >> 3) & 1;

    // q fragments: 4 k-steps x hi/lo
    uint32_t fQh[4][4], fQl[4][4];
    #pragma unroll
    for (int ks = 0; ks < 4; ks++) {
        int row = wid * 16 + a_row_off;
        uint32_t ad = swz128(row, ks * 2 + a_half);
        ldsm_x4(fQh[ks][0], fQh[ks][1], fQh[ks][2], fQh[ks][3], sQh + ad);
        ldsm_x4(fQl[ks][0], fQl[ks][1], fQl[ks][2], fQl[ks][3], sQl + ad);
    }

    float acc[8][4];
    #pragma unroll
    for (int nt = 0; nt < 8; nt++)
        #pragma unroll
        for (int c = 0; c < 4; c++) acc[nt][c] = 0.f;
    float rs0 = 0.f, rs1 = 0.f;
    const float scale = 0.125f;

    #pragma unroll
    for (int kt = 0; kt < 7; kt++) {       // l tiles of 16 (0..111)
        // --- QK scores for n-tiles 2kt, 2kt+1 ---
        float c0[4] = {0.f, 0.f, 0.f, 0.f};
        float c1[4] = {0.f, 0.f, 0.f, 0.f};
        #pragma unroll
        for (int ks = 0; ks < 4; ks++) {
            int row = kt * 16 + b_row_off;
            uint32_t bd = swz128(row, ks * 2 + b_half);
            uint32_t kb0, kb1, kb2, kb3;
            ldsm_x4(kb0, kb1, kb2, kb3, sK + bd);
            mma_f16(c0, fQh[ks], kb0, kb1);
            mma_f16(c1, fQh[ks], kb2, kb3);
            mma_f16(c0, fQl[ks], kb0, kb1);
            mma_f16(c1, fQl[ks], kb2, kb3);
        }
        // --- exp + mask + row sums ---
        float e0[4], e1[4];
        #pragma unroll
        for (int j = 0; j < 4; j++) {
            e0[j] = __expf(c0[j] * scale);
            e1[j] = __expf(c1[j] * scale);
        }
        if (kt == 6) {   // n-tile 13: cols 104..111, mask col >= 109
            float m0v = (104 + 2 * tig <= 108) ? 1.f : 0.f;
            float m1v = (105 + 2 * tig <= 108) ? 1.f : 0.f;
            e1[0] *= m0v; e1[1] *= m1v; e1[2] *= m0v; e1[3] *= m1v;
        }
        rs0 += e0[0] + e0[1] + e1[0] + e1[1];
        rs1 += e0[2] + e0[3] + e1[2] + e1[3];
        // --- p fragment: single fp16 (R14 — no lo split) ---
        uint32_t ah[4];
        ah[0] = h2_bits(__floats2half2_rn(e0[0], e0[1]));
        ah[1] = h2_bits(__floats2half2_rn(e0[2], e0[3]));
        ah[2] = h2_bits(__floats2half2_rn(e1[0], e1[1]));
        ah[3] = h2_bits(__floats2half2_rn(e1[2], e1[3]));
        // --- PV: acc += p @ V^T-tile ---
        #pragma unroll
        for (int g = 0; g < 4; g++) {
            uint32_t bd = (uint32_t)((g * 16 + b_row_off) * 240 +
                                     (kt * 2 + b_half) * 16);
            uint32_t vb0, vb1, vb2, vb3;
            ldsm_x4(vb0, vb1, vb2, vb3, sV + bd);
            mma_f16(acc[g * 2 + 0], ah, vb0, vb1);
            mma_f16(acc[g * 2 + 1], ah, vb2, vb3);
        }
    }

    // quad reduction of row sums
    rs0 += __shfl_xor_sync(0xffffffffu, rs0, 1);
    rs0 += __shfl_xor_sync(0xffffffffu, rs0, 2);
    rs1 += __shfl_xor_sync(0xffffffffu, rs1, 1);
    rs1 += __shfl_xor_sync(0xffffffffu, rs1, 2);
    const float inv0 = 1.f / rs0;
    const float inv1 = 1.f / rs1;

    // epilogue: normalize, store single-fp16 att
    const int r0 = qrow0 + wid * 16 + gid;
    #pragma unroll
    for (int nt = 0; nt < 8; nt++) {
        int col = h * DH + nt * 8 + tig * 2;
        *(__half2*)(g_att + (size_t)r0 * H_ + col) =
            __floats2half2_rn(acc[nt][0] * inv0, acc[nt][1] * inv0);
        *(__half2*)(g_att + (size_t)(r0 + 8) * H_ + col) =
            __floats2half2_rn(acc[nt][2] * inv1, acc[nt][3] * inv1);
    }
}

// ---------------------------------------------------------------------------
// Side streams + events for fork/join inside graph capture (host objects).
// ---------------------------------------------------------------------------
struct SideStreams {
    cudaStream_t s1, s2;
    cudaEvent_t ef1, ef2, e_kv, e_w;
    SideStreams() {
        cudaStreamCreateWithFlags(&s1, cudaStreamNonBlocking);
        cudaStreamCreateWithFlags(&s2, cudaStreamNonBlocking);
        cudaEventCreateWithFlags(&ef1, cudaEventDisableTiming);
        cudaEventCreateWithFlags(&ef2, cudaEventDisableTiming);
        cudaEventCreateWithFlags(&e_kv, cudaEventDisableTiming);
        cudaEventCreateWithFlags(&e_w, cudaEventDisableTiming);
    }
};
static SideStreams& side() { static SideStreams s; return s; }

// ---------------------------------------------------------------------------
extern "C" void kernel_launch(void* const* d_in, const int* in_sizes, int n_in,
                              void* d_out, int out_size)
{
    (void)in_sizes; (void)n_in; (void)out_size;
    const float* hs    = (const float*)d_in[0];
    const float* ehs   = (const float*)d_in[1];
    const float* idemb = (const float*)d_in[2];
    const float* Wq    = (const float*)d_in[3];
    const float* Wk    = (const float*)d_in[4];
    const float* Wv    = (const float*)d_in[5];
    const float* Wid_k = (const float*)d_in[6];
    const float* Wid_v = (const float*)d_in[7];
    const float* Wout  = (const float*)d_in[8];
    const float* bout  = (const float*)d_in[9];
    float* out = (float*)d_out;

    const int attn_smem = ASM_TOT;            // 62,464 B
    const int gemm_smem = NSTAGE * STAGE_B;   // 98,304 B
    cudaFuncSetAttribute(attn_kernel,
                         cudaFuncAttributeMaxDynamicSharedMemorySize, attn_smem);
    cudaFuncSetAttribute(gemm_hmma<0>,
                         cudaFuncAttributeMaxDynamicSharedMemorySize, gemm_smem);
    cudaFuncSetAttribute(gemm_hmma<1>,
                         cudaFuncAttributeMaxDynamicSharedMemorySize, gemm_smem);

    SideStreams& ss = side();

    // Fork: kv on s1, weight transpose on s2, concurrent with critical path.
    cudaEventRecord(ss.ef1, 0);
    cudaStreamWaitEvent(ss.s1, ss.ef1, 0);
    cudaEventRecord(ss.ef2, 0);
    cudaStreamWaitEvent(ss.s2, ss.ef2, 0);

    kv_kernel<<<dim3(H_ / 64, (B_ * T_ + 63) / 64, 4), 256, 0, ss.s1>>>(
        ehs, idemb, Wk, Wv, Wid_k, Wid_v);
    cudaEventRecord(ss.e_kv, ss.s1);

    tsplit_kernel<<<dim3(H_ / 32, H_ / 32, 2), dim3(32, 8), 0, ss.s2>>>(Wq, Wout);
    cudaEventRecord(ss.e_w, ss.s2);

    // Main stream: hidden_states split
    split_kernel<<<(ROWS * H_ / 4 + 255) / 256, 256>>>(hs);

    // gemm0 needs g_wq (join s2)
    cudaStreamWaitEvent(0, ss.e_w, 0);
    gemm_hmma<0><<<dim3(GN / 128, ROWS / 128), 256, gemm_smem>>>(nullptr, nullptr);

    // attention needs K/V (join s1)
    cudaStreamWaitEvent(0, ss.e_kv, 0);
    attn_kernel<<<dim3(S_ / 128, B_ * NHEADS), 256, attn_smem>>>();

    // out = att @ Wout + bout
    gemm_hmma<1><<<dim3(GN / 128, ROWS / 128), 256, gemm_smem>>>(bout, out);
}

// round 15
// speedup vs baseline: 1.6401x; 1.3852x over previous
#include <cuda_runtime.h>
#include <cuda_fp16.h>
#include <cstdint>
#include <math.h>

// Problem constants
#define B_      4
#define S_      4096
#define H_      1280
#define C_      2048
#define T_      77
#define I_      32
#define NHEADS  20
#define DH      64
#define L_      (T_ + I_)       // 109
#define LPAD    112             // K rows padded (mult of 16)
#define LPAD2   120             // V^T row length (240B rows -> conflict-free)
#define ROWS    (B_ * S_)       // 16384

// ---------------------------------------------------------------------------
// Scratch (device globals; zero-initialized; no allocations allowed)
// Precision plan (7 rounding sources x ~2.07e-4 -> rel_err ~5.5e-4):
//   hs single x wq single -> q SPLIT (from fp32 acc, free accuracy)
//   q split x K single (QK), p single x V single (PV), att single
//   att single x wo single (+fp32 bias)
// ---------------------------------------------------------------------------
__device__ __half g_q_hi[ROWS * H_];
__device__ __half g_q_lo[ROWS * H_];
__device__ __half g_att[ROWS * H_];       // attention out, single fp16
__device__ __half g_hs[ROWS * H_];        // hidden_states, single fp16
__device__ __half g_wq[H_ * H_];          // Wq^T [N,K], single fp16
__device__ __half g_wo[H_ * H_];          // Wout^T [N,K], single fp16
__device__ __half g_k[B_ * LPAD * H_];    // K [b][l][n], rows 109..111 zero
__device__ __half g_vt[B_ * H_ * LPAD2];  // V^T [b][n][l], l 109..119 zero

// ---------------------------------------------------------------------------
// PTX helpers (sm_100 base target — NO tcgen05, which needs the 'a' variant)
// ---------------------------------------------------------------------------
#define CP_ASYNC_16(dst, src) \
    asm volatile("cp.async.cg.shared.global [%0], [%1], 16;" :: "r"(dst), "l"(src) : "memory")
#define CP_COMMIT() asm volatile("cp.async.commit_group;" ::: "memory")
#define CP_WAIT2()  asm volatile("cp.async.wait_group 2;" ::: "memory")
#define CP_WAIT0()  asm volatile("cp.async.wait_group 0;" ::: "memory")

__device__ __forceinline__ uint32_t smem_to_u32(const void* p) {
    uint32_t a;
    asm("{ .reg .u64 t; cvta.to.shared.u64 t, %1; cvt.u32.u64 %0, t; }"
        : "=r"(a) : "l"(p));
    return a;
}

__device__ __forceinline__ void ldsm_x4(uint32_t& r0, uint32_t& r1,
                                        uint32_t& r2, uint32_t& r3, uint32_t addr) {
    asm volatile("ldmatrix.sync.aligned.m8n8.x4.shared.b16 {%0,%1,%2,%3}, [%4];"
                 : "=r"(r0), "=r"(r1), "=r"(r2), "=r"(r3) : "r"(addr));
}

__device__ __forceinline__ void mma_f16(float* d, const uint32_t* a,
                                        uint32_t b0, uint32_t b1) {
    asm volatile(
        "mma.sync.aligned.m16n8k16.row.col.f32.f16.f16.f32 "
        "{%0,%1,%2,%3}, {%4,%5,%6,%7}, {%8,%9}, {%0,%1,%2,%3};"
        : "+f"(d[0]), "+f"(d[1]), "+f"(d[2]), "+f"(d[3])
        : "r"(a[0]), "r"(a[1]), "r"(a[2]), "r"(a[3]), "r"(b0), "r"(b1));
}

__device__ __forceinline__ uint32_t h2_bits(__half2 v) {
    return *reinterpret_cast<uint32_t*>(&v);
}

// fp16 two-term split of fp32 (exact to ~2^-22)
__device__ __forceinline__ void f16split(float x, __half& h, __half& l) {
    h = __float2half_rn(x);
    l = __float2half_rn(x - __half2float(h));
}

// ---------------------------------------------------------------------------
// Prep 1: hidden_states -> single fp16
// ---------------------------------------------------------------------------
__global__ void __launch_bounds__(256) split_kernel(const float* __restrict__ src)
{
    size_t i = ((size_t)blockIdx.x * 256 + threadIdx.x) * 4;
    float4 v = *(const float4*)(src + i);
    *(__half2*)(g_hs + i)     = __floats2half2_rn(v.x, v.y);
    *(__half2*)(g_hs + i + 2) = __floats2half2_rn(v.z, v.w);
}

// ---------------------------------------------------------------------------
// Prep 2: transpose weights -> [N, K], single fp16 both
// ---------------------------------------------------------------------------
__global__ void __launch_bounds__(256) tsplit_kernel(const float* __restrict__ Wq,
                                                     const float* __restrict__ Wout)
{
    __shared__ float t[32][33];
    const bool is_wo = blockIdx.z != 0;
    const float* W = is_wo ? Wout : Wq;
    __half* dst = is_wo ? g_wo : g_wq;
    int bx = blockIdx.x * 32, by = blockIdx.y * 32;
    int tx = threadIdx.x, ty = threadIdx.y;
    #pragma unroll
    for (int i = 0; i < 4; i++)
        t[ty + 8 * i][tx] = W[(size_t)(by + ty + 8 * i) * H_ + bx + tx];
    __syncthreads();
    #pragma unroll
    for (int i = 0; i < 4; i++) {
        size_t o = (size_t)(bx + ty + 8 * i) * H_ + by + tx;   // [n][k]
        dst[o] = __float2half_rn(t[tx][ty + 8 * i]);
    }
}

// ---------------------------------------------------------------------------
// KV build: fp32 SIMT GEMM; K -> [b][LPAD][H_] fp16, V -> V^T [b][H_][LPAD2].
// ---------------------------------------------------------------------------
__device__ __forceinline__ void kv_store(bool is_v, int b, int l, int n,
                                         const float* vals)
{
    if (!is_v) {
        size_t a = ((size_t)b * LPAD + l) * H_ + n;
        *(__half2*)(g_k + a)     = __floats2half2_rn(vals[0], vals[1]);
        *(__half2*)(g_k + a + 2) = __floats2half2_rn(vals[2], vals[3]);
    } else {
        #pragma unroll
        for (int j = 0; j < 4; j++)
            g_vt[((size_t)b * H_ + n + j) * LPAD2 + l] = __float2half_rn(vals[j]);
    }
}

__global__ void __launch_bounds__(256) kv_kernel(
    const float* __restrict__ ehs, const float* __restrict__ idemb,
    const float* __restrict__ Wk, const float* __restrict__ Wv,
    const float* __restrict__ Wid_k, const float* __restrict__ Wid_v)
{
    const int z = blockIdx.z;
    const bool is_id = (z >= 2);
    const bool is_v  = (z & 1);
    const float* A = is_id ? idemb : ehs;
    const float* W = is_id ? (is_v ? Wid_v : Wid_k) : (is_v ? Wv : Wk);
    const int Mloc = is_id ? (2 * I_) : (B_ * T_);

    const int m0 = blockIdx.y * 64;
    if (m0 >= Mloc) return;
    const int n0 = blockIdx.x * 64;

    __shared__ float As[16][68];
    __shared__ float Bs[16][64];

    const int tid  = threadIdx.x;
    const int arow = tid >> 2;
    const int ac4  = (tid & 3) * 4;
    const int brow = tid >> 4;
    const int bc4  = (tid & 15) * 4;
    const int tx   = tid & 15;
    const int ty   = tid >> 4;

    float acc[4][4];
    #pragma unroll
    for (int i = 0; i < 4; i++)
        #pragma unroll
        for (int j = 0; j < 4; j++) acc[i][j] = 0.f;

    for (int k0 = 0; k0 < C_; k0 += 16) {
        float4 av = make_float4(0.f, 0.f, 0.f, 0.f);
        if (m0 + arow < Mloc)
            av = *(const float4*)(A + (size_t)(m0 + arow) * C_ + k0 + ac4);
        float4 bv = *(const float4*)(W + (size_t)(k0 + brow) * H_ + n0 + bc4);
        __syncthreads();
        As[ac4 + 0][arow] = av.x;
        As[ac4 + 1][arow] = av.y;
        As[ac4 + 2][arow] = av.z;
        As[ac4 + 3][arow] = av.w;
        *(float4*)&Bs[brow][bc4] = bv;
        __syncthreads();
        #pragma unroll
        for (int kk = 0; kk < 16; kk++) {
            float4 a = *(const float4*)&As[kk][ty * 4];
            float4 b = *(const float4*)&Bs[kk][tx * 4];
            float am[4] = {a.x, a.y, a.z, a.w};
            float bn[4] = {b.x, b.y, b.z, b.w};
            #pragma unroll
            for (int i = 0; i < 4; i++)
                #pragma unroll
                for (int j = 0; j < 4; j++)
                    acc[i][j] += am[i] * bn[j];
        }
    }

    #pragma unroll
    for (int i = 0; i < 4; i++) {
        int r = m0 + ty * 4 + i;
        if (r >= Mloc) continue;
        if (!is_id) {
            int batch = r / T_, pos = r % T_;
            kv_store(is_v, batch, pos, n0 + tx * 4, acc[i]);
        } else {
            int hb = r >> 5, ii = r & 31;
            kv_store(is_v, hb,     T_ + ii, n0 + tx * 4, acc[i]);
            kv_store(is_v, hb + 2, T_ + ii, n0 + tx * 4, acc[i]);
        }
    }
}

// ---------------------------------------------------------------------------
// HMMA fp16 GEMM, single x single (R15: 1 MMA product — half of R14).
// CTA 128x128, BK=32, 8 warps (4x2), warp 32x64, 2 CTAs/SM, 4-stage
// cp.async (wait 2), R6 ordering. 2 smem tiles/stage (A, B).
// MODE 0: hs x wq -> q fp16 splits (from fp32 acc).
// MODE 1: att x wo -> fp32 + bias to Cp.
// ---------------------------------------------------------------------------
#define GK       H_          // 1280
#define GN       H_          // 1280
#define BK       32
#define NIT      (GK / BK)   // 40
#define TILE_B   (128 * 64)  // 8192 B
#define STAGE_B  (2 * TILE_B)   // 16384 B
#define NSTAGE   4

__device__ __forceinline__ uint32_t swz(int row, int chunk) {
    return (uint32_t)(row * 64 + ((chunk ^ ((row >> 1) & 3)) << 4));
}

__device__ __forceinline__ void fill_tile(uint32_t dst, const __half* src,
                                          int k0, int tid)
{
    #pragma unroll
    for (int i = 0; i < 2; i++) {
        int idx = i * 256 + tid;
        int row = idx >> 2;
        int c   = idx & 3;
        CP_ASYNC_16(dst + swz(row, c),
                    src + (size_t)row * GK + k0 + c * 8);
    }
}

template<int MODE>
__global__ void __launch_bounds__(256, 2) gemm_hmma(
    const float* __restrict__ bias, float* __restrict__ Cp)
{
    const __half* Ap = (MODE == 0) ? g_hs : g_att;
    const __half* Bp = (MODE == 0) ? g_wq : g_wo;

    extern __shared__ char smem[];
    const uint32_t sb = smem_to_u32(smem);

    const int tid  = threadIdx.x;
    const int wid  = tid >> 5;
    const int lane = tid & 31;
    const int wm   = wid >> 1;
    const int wn   = wid & 1;
    const int n0 = blockIdx.x * 128;
    const int m0 = blockIdx.y * 128;

    const __half* aP = Ap + (size_t)m0 * GK;
    const __half* bP = Bp + (size_t)n0 * GK;

    const int a_row_off = (lane & 7) + ((lane >> 3) & 1) * 8;
    const int a_half    = lane >> 4;
    const int b_row_off = (lane & 7) + ((lane >> 4) & 1) * 8;
    const int b_half    = (lane >> 3) & 1;

    float acc[2][8][4];
    #pragma unroll
    for (int mt = 0; mt < 2; mt++)
        #pragma unroll
        for (int nt = 0; nt < 8; nt++)
            #pragma unroll
            for (int c = 0; c < 4; c++) acc[mt][nt][c] = 0.f;

    #pragma unroll
    for (int st = 0; st < NSTAGE - 1; st++) {
        uint32_t s = sb + st * STAGE_B;
        fill_tile(s + 0 * TILE_B, aP, st * BK, tid);
        fill_tile(s + 1 * TILE_B, bP, st * BK, tid);
        CP_COMMIT();
    }

    int stage = 0;
    for (int it = 0; it < NIT; it++) {
        uint32_t s = sb + stage * STAGE_B;
        CP_WAIT2();
        __syncthreads();

        const uint32_t sA = s + 0 * TILE_B;
        const uint32_t sB = s + 1 * TILE_B;

        #pragma unroll
        for (int ks = 0; ks < 2; ks++) {
            uint32_t fA[2][4];
            #pragma unroll
            for (int mt = 0; mt < 2; mt++) {
                int row = wm * 32 + mt * 16 + a_row_off;
                uint32_t ad = swz(row, ks * 2 + a_half);
                ldsm_x4(fA[mt][0], fA[mt][1], fA[mt][2], fA[mt][3], sA + ad);
            }
            #pragma unroll
            for (int g = 0; g < 4; g++) {
                int row = wn * 64 + g * 16 + b_row_off;
                uint32_t bd = swz(row, ks * 2 + b_half);
                uint32_t b0, b1, b2, b3;
                ldsm_x4(b0, b1, b2, b3, sB + bd);
                #pragma unroll
                for (int mt = 0; mt < 2; mt++) {
                    mma_f16(acc[mt][g * 2 + 0], fA[mt], b0, b1);
                    mma_f16(acc[mt][g * 2 + 1], fA[mt], b2, b3);
                }
            }
        }

        if (it + NSTAGE - 1 < NIT) {
            int fs = stage + NSTAGE - 1;
            if (fs >= NSTAGE) fs -= NSTAGE;
            uint32_t f = sb + fs * STAGE_B;
            int k0 = (it + NSTAGE - 1) * BK;
            fill_tile(f + 0 * TILE_B, aP, k0, tid);
            fill_tile(f + 1 * TILE_B, bP, k0, tid);
        }
        CP_COMMIT();
        stage = stage + 1 >= NSTAGE ? 0 : stage + 1;
    }

    // Epilogue
    const int gid = lane >> 2, tig = lane & 3;
    #pragma unroll
    for (int mt = 0; mt < 2; mt++) {
        #pragma unroll
        for (int nt = 0; nt < 8; nt++) {
            int r   = m0 + wm * 32 + mt * 16 + gid;
            int col = n0 + wn * 64 + nt * 8 + tig * 2;
            if (MODE == 0) {
                #pragma unroll
                for (int half = 0; half < 2; half++) {
                    int rr = r + half * 8;
                    __half h0, l0, h1, l1;
                    f16split(acc[mt][nt][half * 2 + 0], h0, l0);
                    f16split(acc[mt][nt][half * 2 + 1], h1, l1);
                    size_t a = (size_t)rr * GN + col;
                    *(__half2*)(g_q_hi + a) = __half2(h0, h1);
                    *(__half2*)(g_q_lo + a) = __half2(l0, l1);
                }
            } else {
                float b0v = bias[col], b1v = bias[col + 1];
                float2 v0 = make_float2(acc[mt][nt][0] + b0v, acc[mt][nt][1] + b1v);
                float2 v1 = make_float2(acc[mt][nt][2] + b0v, acc[mt][nt][3] + b1v);
                *(float2*)(Cp + (size_t)r * GN + col)       = v0;
                *(float2*)(Cp + (size_t)(r + 8) * GN + col) = v1;
            }
        }
    }
}

// ---------------------------------------------------------------------------
// HMMA flash attention (R14 version: q split x K single, p single x V single,
// single-fp16 att output). CTA = 128 queries x one (b,h), 2560 CTAs.
// ---------------------------------------------------------------------------
#define ASM_Q   0
#define ASM_K   (2 * 128 * 128)                 // 32768
#define ASM_V   (ASM_K + LPAD * 128)            // 47104
#define ASM_TOT (ASM_V + 64 * 240)              // 62464

__device__ __forceinline__ uint32_t swz128(int row, int chunk) {
    return (uint32_t)(row * 128 + ((chunk ^ (row & 7)) << 4));
}

__global__ void __launch_bounds__(256, 2) attn_kernel()
{
    extern __shared__ char asmem[];
    const uint32_t sb = smem_to_u32(asmem);
    const uint32_t sQh = sb + ASM_Q,  sQl = sQh + 128 * 128;
    const uint32_t sK  = sb + ASM_K;
    const uint32_t sV  = sb + ASM_V;

    const int tid  = threadIdx.x;
    const int wid  = tid >> 5;
    const int lane = tid & 31;
    const int bh = blockIdx.y;
    const int batch = bh / NHEADS;
    const int h = bh % NHEADS;
    const int qrow0 = batch * S_ + blockIdx.x * 128;

    // ---- loads (one-shot, cp.async) ----
    {
        const __half* qh = g_q_hi + (size_t)qrow0 * H_ + h * DH;
        const __half* ql = g_q_lo + (size_t)qrow0 * H_ + h * DH;
        #pragma unroll
        for (int i = 0; i < 4; i++) {
            int idx = i * 256 + tid;            // 0..1023
            int row = idx >> 3, c = idx & 7;
            CP_ASYNC_16(sQh + swz128(row, c), qh + (size_t)row * H_ + c * 8);
            CP_ASYNC_16(sQl + swz128(row, c), ql + (size_t)row * H_ + c * 8);
        }
        const __half* kp = g_k + (size_t)batch * LPAD * H_ + h * DH;
        for (int idx = tid; idx < LPAD * 8; idx += 256) {
            int row = idx >> 3, c = idx & 7;
            CP_ASYNC_16(sK + swz128(row, c), kp + (size_t)row * H_ + c * 8);
        }
        const __half* vp = g_vt + ((size_t)batch * H_ + h * DH) * LPAD2;
        for (int idx = tid; idx < 64 * 14; idx += 256) {
            int row = idx / 14, c = idx % 14;
            CP_ASYNC_16(sV + (uint32_t)(row * 240 + c * 16),
                        vp + (size_t)row * LPAD2 + c * 8);
        }
        CP_COMMIT();
    }
    CP_WAIT0();
    __syncthreads();

    const int gid = lane >> 2, tig = lane & 3;
    const int a_row_off = (lane & 7) + ((lane >> 3) & 1) * 8;
    const int a_half    = lane >> 4;
    const int b_row_off = (lane & 7) + ((lane >> 4) & 1) * 8;
    const int b_half    = (lane >> 3) & 1;

    // q fragments: 4 k-steps x hi/lo
    uint32_t fQh[4][4], fQl[4][4];
    #pragma unroll
    for (int ks = 0; ks < 4; ks++) {
        int row = wid * 16 + a_row_off;
        uint32_t ad = swz128(row, ks * 2 + a_half);
        ldsm_x4(fQh[ks][0], fQh[ks][1], fQh[ks][2], fQh[ks][3], sQh + ad);
        ldsm_x4(fQl[ks][0], fQl[ks][1], fQl[ks][2], fQl[ks][3], sQl + ad);
    }

    float acc[8][4];
    #pragma unroll
    for (int nt = 0; nt < 8; nt++)
        #pragma unroll
        for (int c = 0; c < 4; c++) acc[nt][c] = 0.f;
    float rs0 = 0.f, rs1 = 0.f;
    const float scale = 0.125f;

    #pragma unroll
    for (int kt = 0; kt < 7; kt++) {       // l tiles of 16 (0..111)
        float c0[4] = {0.f, 0.f, 0.f, 0.f};
        float c1[4] = {0.f, 0.f, 0.f, 0.f};
        #pragma unroll
        for (int ks = 0; ks < 4; ks++) {
            int row = kt * 16 + b_row_off;
            uint32_t bd = swz128(row, ks * 2 + b_half);
            uint32_t kb0, kb1, kb2, kb3;
            ldsm_x4(kb0, kb1, kb2, kb3, sK + bd);
            mma_f16(c0, fQh[ks], kb0, kb1);
            mma_f16(c1, fQh[ks], kb2, kb3);
            mma_f16(c0, fQl[ks], kb0, kb1);
            mma_f16(c1, fQl[ks], kb2, kb3);
        }
        float e0[4], e1[4];
        #pragma unroll
        for (int j = 0; j < 4; j++) {
            e0[j] = __expf(c0[j] * scale);
            e1[j] = __expf(c1[j] * scale);
        }
        if (kt == 6) {   // n-tile 13: cols 104..111, mask col >= 109
            float m0v = (104 + 2 * tig <= 108) ? 1.f : 0.f;
            float m1v = (105 + 2 * tig <= 108) ? 1.f : 0.f;
            e1[0] *= m0v; e1[1] *= m1v; e1[2] *= m0v; e1[3] *= m1v;
        }
        rs0 += e0[0] + e0[1] + e1[0] + e1[1];
        rs1 += e0[2] + e0[3] + e1[2] + e1[3];
        uint32_t ah[4];
        ah[0] = h2_bits(__floats2half2_rn(e0[0], e0[1]));
        ah[1] = h2_bits(__floats2half2_rn(e0[2], e0[3]));
        ah[2] = h2_bits(__floats2half2_rn(e1[0], e1[1]));
        ah[3] = h2_bits(__floats2half2_rn(e1[2], e1[3]));
        #pragma unroll
        for (int g = 0; g < 4; g++) {
            uint32_t bd = (uint32_t)((g * 16 + b_row_off) * 240 +
                                     (kt * 2 + b_half) * 16);
            uint32_t vb0, vb1, vb2, vb3;
            ldsm_x4(vb0, vb1, vb2, vb3, sV + bd);
            mma_f16(acc[g * 2 + 0], ah, vb0, vb1);
            mma_f16(acc[g * 2 + 1], ah, vb2, vb3);
        }
    }

    rs0 += __shfl_xor_sync(0xffffffffu, rs0, 1);
    rs0 += __shfl_xor_sync(0xffffffffu, rs0, 2);
    rs1 += __shfl_xor_sync(0xffffffffu, rs1, 1);
    rs1 += __shfl_xor_sync(0xffffffffu, rs1, 2);
    const float inv0 = 1.f / rs0;
    const float inv1 = 1.f / rs1;

    const int r0 = qrow0 + wid * 16 + gid;
    #pragma unroll
    for (int nt = 0; nt < 8; nt++) {
        int col = h * DH + nt * 8 + tig * 2;
        *(__half2*)(g_att + (size_t)r0 * H_ + col) =
            __floats2half2_rn(acc[nt][0] * inv0, acc[nt][1] * inv0);
        *(__half2*)(g_att + (size_t)(r0 + 8) * H_ + col) =
            __floats2half2_rn(acc[nt][2] * inv1, acc[nt][3] * inv1);
    }
}

// ---------------------------------------------------------------------------
// Side streams + events for fork/join inside graph capture (host objects).
// ---------------------------------------------------------------------------
struct SideStreams {
    cudaStream_t s1, s2;
    cudaEvent_t ef1, ef2, e_kv, e_w;
    SideStreams() {
        cudaStreamCreateWithFlags(&s1, cudaStreamNonBlocking);
        cudaStreamCreateWithFlags(&s2, cudaStreamNonBlocking);
        cudaEventCreateWithFlags(&ef1, cudaEventDisableTiming);
        cudaEventCreateWithFlags(&ef2, cudaEventDisableTiming);
        cudaEventCreateWithFlags(&e_kv, cudaEventDisableTiming);
        cudaEventCreateWithFlags(&e_w, cudaEventDisableTiming);
    }
};
static SideStreams& side() { static SideStreams s; return s; }

// ---------------------------------------------------------------------------
extern "C" void kernel_launch(void* const* d_in, const int* in_sizes, int n_in,
                              void* d_out, int out_size)
{
    (void)in_sizes; (void)n_in; (void)out_size;
    const float* hs    = (const float*)d_in[0];
    const float* ehs   = (const float*)d_in[1];
    const float* idemb = (const float*)d_in[2];
    const float* Wq    = (const float*)d_in[3];
    const float* Wk    = (const float*)d_in[4];
    const float* Wv    = (const float*)d_in[5];
    const float* Wid_k = (const float*)d_in[6];
    const float* Wid_v = (const float*)d_in[7];
    const float* Wout  = (const float*)d_in[8];
    const float* bout  = (const float*)d_in[9];
    float* out = (float*)d_out;

    const int attn_smem = ASM_TOT;            // 62,464 B
    const int gemm_smem = NSTAGE * STAGE_B;   // 65,536 B
    cudaFuncSetAttribute(attn_kernel,
                         cudaFuncAttributeMaxDynamicSharedMemorySize, attn_smem);
    cudaFuncSetAttribute(gemm_hmma<0>,
                         cudaFuncAttributeMaxDynamicSharedMemorySize, gemm_smem);
    cudaFuncSetAttribute(gemm_hmma<1>,
                         cudaFuncAttributeMaxDynamicSharedMemorySize, gemm_smem);

    SideStreams& ss = side();

    // Fork: kv on s1, weight transpose on s2, concurrent with critical path.
    cudaEventRecord(ss.ef1, 0);
    cudaStreamWaitEvent(ss.s1, ss.ef1, 0);
    cudaEventRecord(ss.ef2, 0);
    cudaStreamWaitEvent(ss.s2, ss.ef2, 0);

    kv_kernel<<<dim3(H_ / 64, (B_ * T_ + 63) / 64, 4), 256, 0, ss.s1>>>(
        ehs, idemb, Wk, Wv, Wid_k, Wid_v);
    cudaEventRecord(ss.e_kv, ss.s1);

    tsplit_kernel<<<dim3(H_ / 32, H_ / 32, 2), dim3(32, 8), 0, ss.s2>>>(Wq, Wout);
    cudaEventRecord(ss.e_w, ss.s2);

    // Main stream: hidden_states -> fp16
    split_kernel<<<(ROWS * H_ / 4 + 255) / 256, 256>>>(hs);

    // gemm0 needs g_wq (join s2)
    cudaStreamWaitEvent(0, ss.e_w, 0);
    gemm_hmma<0><<<dim3(GN / 128, ROWS / 128), 256, gemm_smem>>>(nullptr, nullptr);

    // attention needs K/V (join s1)
    cudaStreamWaitEvent(0, ss.e_kv, 0);
    attn_kernel<<<dim3(S_ / 128, B_ * NHEADS), 256, attn_smem>>>();

    // out = att @ Wout + bout
    gemm_hmma<1><<<dim3(GN / 128, ROWS / 128), 256, gemm_smem>>>(bout, out);
}

// round 16
// speedup vs baseline: 1.7503x; 1.0672x over previous
#include <cuda_runtime.h>
#include <cuda_fp16.h>
#include <cstdint>
#include <math.h>

// Problem constants
#define B_      4
#define S_      4096
#define H_      1280
#define C_      2048
#define T_      77
#define I_      32
#define NHEADS  20
#define DH      64
#define L_      (T_ + I_)       // 109
#define LPAD    112             // K rows padded (mult of 16)
#define LPAD2   120             // V^T row length (240B rows -> conflict-free)
#define ROWS    (B_ * S_)       // 16384

// ---------------------------------------------------------------------------
// Scratch (device globals; zero-initialized; no allocations allowed)
// Precision plan (8 rounding sources x ~2.07e-4 -> rel_err ~5.9e-4):
// all operands single fp16, fp32 accumulation everywhere, fp32 bias.
// ---------------------------------------------------------------------------
__device__ __half g_q[ROWS * H_];         // q projection, single fp16
__device__ __half g_att[ROWS * H_];       // attention out, single fp16
__device__ __half g_hs[ROWS * H_];        // hidden_states, single fp16
__device__ __half g_wq[H_ * H_];          // Wq^T [N,K]
__device__ __half g_wo[H_ * H_];          // Wout^T [N,K]
__device__ __half g_k[B_ * LPAD * H_];    // K [b][l][n], rows 109..111 zero
__device__ __half g_vt[B_ * H_ * LPAD2];  // V^T [b][n][l], l 109..119 zero

// ---------------------------------------------------------------------------
// PTX helpers (sm_100 base target — NO tcgen05, which needs the 'a' variant)
// ---------------------------------------------------------------------------
#define CP_ASYNC_16(dst, src) \
    asm volatile("cp.async.cg.shared.global [%0], [%1], 16;" :: "r"(dst), "l"(src) : "memory")
#define CP_COMMIT() asm volatile("cp.async.commit_group;" ::: "memory")
#define CP_WAIT1()  asm volatile("cp.async.wait_group 1;" ::: "memory")
#define CP_WAIT0()  asm volatile("cp.async.wait_group 0;" ::: "memory")

__device__ __forceinline__ uint32_t smem_to_u32(const void* p) {
    uint32_t a;
    asm("{ .reg .u64 t; cvta.to.shared.u64 t, %1; cvt.u32.u64 %0, t; }"
        : "=r"(a) : "l"(p));
    return a;
}

__device__ __forceinline__ void ldsm_x4(uint32_t& r0, uint32_t& r1,
                                        uint32_t& r2, uint32_t& r3, uint32_t addr) {
    asm volatile("ldmatrix.sync.aligned.m8n8.x4.shared.b16 {%0,%1,%2,%3}, [%4];"
                 : "=r"(r0), "=r"(r1), "=r"(r2), "=r"(r3) : "r"(addr));
}

__device__ __forceinline__ void mma_f16(float* d, const uint32_t* a,
                                        uint32_t b0, uint32_t b1) {
    asm volatile(
        "mma.sync.aligned.m16n8k16.row.col.f32.f16.f16.f32 "
        "{%0,%1,%2,%3}, {%4,%5,%6,%7}, {%8,%9}, {%0,%1,%2,%3};"
        : "+f"(d[0]), "+f"(d[1]), "+f"(d[2]), "+f"(d[3])
        : "r"(a[0]), "r"(a[1]), "r"(a[2]), "r"(a[3]), "r"(b0), "r"(b1));
}

__device__ __forceinline__ uint32_t h2_bits(__half2 v) {
    return *reinterpret_cast<uint32_t*>(&v);
}

// 128B-row XOR swizzle (8 x 16B chunks, proven conflict-free for both
// cp.async stores and ldsm chunk addressing)
__device__ __forceinline__ uint32_t swz128(int row, int chunk) {
    return (uint32_t)(row * 128 + ((chunk ^ (row & 7)) << 4));
}

// ---------------------------------------------------------------------------
// Prep 1: hidden_states -> single fp16
// ---------------------------------------------------------------------------
__global__ void __launch_bounds__(256) split_kernel(const float* __restrict__ src)
{
    size_t i = ((size_t)blockIdx.x * 256 + threadIdx.x) * 4;
    float4 v = *(const float4*)(src + i);
    *(__half2*)(g_hs + i)     = __floats2half2_rn(v.x, v.y);
    *(__half2*)(g_hs + i + 2) = __floats2half2_rn(v.z, v.w);
}

// ---------------------------------------------------------------------------
// Prep 2: transpose weights -> [N, K], single fp16 both
// ---------------------------------------------------------------------------
__global__ void __launch_bounds__(256) tsplit_kernel(const float* __restrict__ Wq,
                                                     const float* __restrict__ Wout)
{
    __shared__ float t[32][33];
    const bool is_wo = blockIdx.z != 0;
    const float* W = is_wo ? Wout : Wq;
    __half* dst = is_wo ? g_wo : g_wq;
    int bx = blockIdx.x * 32, by = blockIdx.y * 32;
    int tx = threadIdx.x, ty = threadIdx.y;
    #pragma unroll
    for (int i = 0; i < 4; i++)
        t[ty + 8 * i][tx] = W[(size_t)(by + ty + 8 * i) * H_ + bx + tx];
    __syncthreads();
    #pragma unroll
    for (int i = 0; i < 4; i++) {
        size_t o = (size_t)(bx + ty + 8 * i) * H_ + by + tx;   // [n][k]
        dst[o] = __float2half_rn(t[tx][ty + 8 * i]);
    }
}

// ---------------------------------------------------------------------------
// KV build: fp32 SIMT GEMM; K -> [b][LPAD][H_] fp16, V -> V^T [b][H_][LPAD2].
// ---------------------------------------------------------------------------
__device__ __forceinline__ void kv_store(bool is_v, int b, int l, int n,
                                         const float* vals)
{
    if (!is_v) {
        size_t a = ((size_t)b * LPAD + l) * H_ + n;
        *(__half2*)(g_k + a)     = __floats2half2_rn(vals[0], vals[1]);
        *(__half2*)(g_k + a + 2) = __floats2half2_rn(vals[2], vals[3]);
    } else {
        #pragma unroll
        for (int j = 0; j < 4; j++)
            g_vt[((size_t)b * H_ + n + j) * LPAD2 + l] = __float2half_rn(vals[j]);
    }
}

__global__ void __launch_bounds__(256) kv_kernel(
    const float* __restrict__ ehs, const float* __restrict__ idemb,
    const float* __restrict__ Wk, const float* __restrict__ Wv,
    const float* __restrict__ Wid_k, const float* __restrict__ Wid_v)
{
    const int z = blockIdx.z;
    const bool is_id = (z >= 2);
    const bool is_v  = (z & 1);
    const float* A = is_id ? idemb : ehs;
    const float* W = is_id ? (is_v ? Wid_v : Wid_k) : (is_v ? Wv : Wk);
    const int Mloc = is_id ? (2 * I_) : (B_ * T_);

    const int m0 = blockIdx.y * 64;
    if (m0 >= Mloc) return;
    const int n0 = blockIdx.x * 64;

    __shared__ float As[16][68];
    __shared__ float Bs[16][64];

    const int tid  = threadIdx.x;
    const int arow = tid >> 2;
    const int ac4  = (tid & 3) * 4;
    const int brow = tid >> 4;
    const int bc4  = (tid & 15) * 4;
    const int tx   = tid & 15;
    const int ty   = tid >> 4;

    float acc[4][4];
    #pragma unroll
    for (int i = 0; i < 4; i++)
        #pragma unroll
        for (int j = 0; j < 4; j++) acc[i][j] = 0.f;

    for (int k0 = 0; k0 < C_; k0 += 16) {
        float4 av = make_float4(0.f, 0.f, 0.f, 0.f);
        if (m0 + arow < Mloc)
            av = *(const float4*)(A + (size_t)(m0 + arow) * C_ + k0 + ac4);
        float4 bv = *(const float4*)(W + (size_t)(k0 + brow) * H_ + n0 + bc4);
        __syncthreads();
        As[ac4 + 0][arow] = av.x;
        As[ac4 + 1][arow] = av.y;
        As[ac4 + 2][arow] = av.z;
        As[ac4 + 3][arow] = av.w;
        *(float4*)&Bs[brow][bc4] = bv;
        __syncthreads();
        #pragma unroll
        for (int kk = 0; kk < 16; kk++) {
            float4 a = *(const float4*)&As[kk][ty * 4];
            float4 b = *(const float4*)&Bs[kk][tx * 4];
            float am[4] = {a.x, a.y, a.z, a.w};
            float bn[4] = {b.x, b.y, b.z, b.w};
            #pragma unroll
            for (int i = 0; i < 4; i++)
                #pragma unroll
                for (int j = 0; j < 4; j++)
                    acc[i][j] += am[i] * bn[j];
        }
    }

    #pragma unroll
    for (int i = 0; i < 4; i++) {
        int r = m0 + ty * 4 + i;
        if (r >= Mloc) continue;
        if (!is_id) {
            int batch = r / T_, pos = r % T_;
            kv_store(is_v, batch, pos, n0 + tx * 4, acc[i]);
        } else {
            int hb = r >> 5, ii = r & 31;
            kv_store(is_v, hb,     T_ + ii, n0 + tx * 4, acc[i]);
            kv_store(is_v, hb + 2, T_ + ii, n0 + tx * 4, acc[i]);
        }
    }
}

// ---------------------------------------------------------------------------
// HMMA fp16 GEMM, single x single. R16: BK=64 (128B rows, swz128) — 20
// iterations instead of 40, halving barrier/wait overhead per MMA.
// CTA 128x128, 8 warps (4x2), warp 32x64, 2 CTAs/SM, 3 stages (96KB).
// MODE 0: hs x wq -> q single fp16. MODE 1: att x wo -> fp32 + bias to Cp.
// ---------------------------------------------------------------------------
#define GK       H_          // 1280
#define GN       H_          // 1280
#define BK       64
#define NIT      (GK / BK)   // 20
#define TILE_B   (128 * 128) // 16384 B per tile
#define STAGE_B  (2 * TILE_B)   // 32768 B
#define NSTAGE   3

__device__ __forceinline__ void fill_tile128(uint32_t dst, const __half* src,
                                             int k0, int tid)
{
    #pragma unroll
    for (int i = 0; i < 4; i++) {
        int idx = i * 256 + tid;       // 0..1023
        int row = idx >> 3;            // 0..127
        int c   = idx & 7;             // 16B chunk
        CP_ASYNC_16(dst + swz128(row, c),
                    src + (size_t)row * GK + k0 + c * 8);
    }
}

template<int MODE>
__global__ void __launch_bounds__(256, 2) gemm_hmma(
    const float* __restrict__ bias, float* __restrict__ Cp)
{
    const __half* Ap = (MODE == 0) ? g_hs : g_att;
    const __half* Bp = (MODE == 0) ? g_wq : g_wo;

    extern __shared__ char smem[];
    const uint32_t sb = smem_to_u32(smem);

    const int tid  = threadIdx.x;
    const int wid  = tid >> 5;
    const int lane = tid & 31;
    const int wm   = wid >> 1;
    const int wn   = wid & 1;
    const int n0 = blockIdx.x * 128;
    const int m0 = blockIdx.y * 128;

    const __half* aP = Ap + (size_t)m0 * GK;
    const __half* bP = Bp + (size_t)n0 * GK;

    const int a_row_off = (lane & 7) + ((lane >> 3) & 1) * 8;
    const int a_half    = lane >> 4;
    const int b_row_off = (lane & 7) + ((lane >> 4) & 1) * 8;
    const int b_half    = (lane >> 3) & 1;

    float acc[2][8][4];
    #pragma unroll
    for (int mt = 0; mt < 2; mt++)
        #pragma unroll
        for (int nt = 0; nt < 8; nt++)
            #pragma unroll
            for (int c = 0; c < 4; c++) acc[mt][nt][c] = 0.f;

    #pragma unroll
    for (int st = 0; st < NSTAGE - 1; st++) {
        uint32_t s = sb + st * STAGE_B;
        fill_tile128(s,          aP, st * BK, tid);
        fill_tile128(s + TILE_B, bP, st * BK, tid);
        CP_COMMIT();
    }

    int stage = 0;
    for (int it = 0; it < NIT; it++) {
        uint32_t s = sb + stage * STAGE_B;
        CP_WAIT1();
        __syncthreads();

        const uint32_t sA = s;
        const uint32_t sB = s + TILE_B;

        #pragma unroll
        for (int ks = 0; ks < 4; ks++) {   // 4 k16 steps in BK=64
            uint32_t fA[2][4];
            #pragma unroll
            for (int mt = 0; mt < 2; mt++) {
                int row = wm * 32 + mt * 16 + a_row_off;
                uint32_t ad = swz128(row, ks * 2 + a_half);
                ldsm_x4(fA[mt][0], fA[mt][1], fA[mt][2], fA[mt][3], sA + ad);
            }
            #pragma unroll
            for (int g = 0; g < 4; g++) {
                int row = wn * 64 + g * 16 + b_row_off;
                uint32_t bd = swz128(row, ks * 2 + b_half);
                uint32_t b0, b1, b2, b3;
                ldsm_x4(b0, b1, b2, b3, sB + bd);
                #pragma unroll
                for (int mt = 0; mt < 2; mt++) {
                    mma_f16(acc[mt][g * 2 + 0], fA[mt], b0, b1);
                    mma_f16(acc[mt][g * 2 + 1], fA[mt], b2, b3);
                }
            }
        }

        if (it + NSTAGE - 1 < NIT) {
            int fs = stage + NSTAGE - 1;
            if (fs >= NSTAGE) fs -= NSTAGE;
            uint32_t f = sb + fs * STAGE_B;
            int k0 = (it + NSTAGE - 1) * BK;
            fill_tile128(f,          aP, k0, tid);
            fill_tile128(f + TILE_B, bP, k0, tid);
        }
        CP_COMMIT();
        stage = stage + 1 >= NSTAGE ? 0 : stage + 1;
    }

    // Epilogue
    const int gid = lane >> 2, tig = lane & 3;
    #pragma unroll
    for (int mt = 0; mt < 2; mt++) {
        #pragma unroll
        for (int nt = 0; nt < 8; nt++) {
            int r   = m0 + wm * 32 + mt * 16 + gid;
            int col = n0 + wn * 64 + nt * 8 + tig * 2;
            if (MODE == 0) {
                *(__half2*)(g_q + (size_t)r * GN + col) =
                    __floats2half2_rn(acc[mt][nt][0], acc[mt][nt][1]);
                *(__half2*)(g_q + (size_t)(r + 8) * GN + col) =
                    __floats2half2_rn(acc[mt][nt][2], acc[mt][nt][3]);
            } else {
                float b0v = bias[col], b1v = bias[col + 1];
                float2 v0 = make_float2(acc[mt][nt][0] + b0v, acc[mt][nt][1] + b1v);
                float2 v1 = make_float2(acc[mt][nt][2] + b0v, acc[mt][nt][3] + b1v);
                *(float2*)(Cp + (size_t)r * GN + col)       = v0;
                *(float2*)(Cp + (size_t)(r + 8) * GN + col) = v1;
            }
        }
    }
}

// ---------------------------------------------------------------------------
// HMMA flash attention, all single fp16 (R16: q split dropped — QK MMAs
// halve, Q smem/loads halve). CTA = 128 queries x one (b,h), 2560 CTAs.
// Smem: Q 16KB | K 14KB | V 15KB = 46080 B.
// ---------------------------------------------------------------------------
#define ASM_Q   0
#define ASM_K   (128 * 128)                     // 16384
#define ASM_V   (ASM_K + LPAD * 128)            // 30720
#define ASM_TOT (ASM_V + 64 * 240)              // 46080

__global__ void __launch_bounds__(256, 2) attn_kernel()
{
    extern __shared__ char asmem[];
    const uint32_t sb = smem_to_u32(asmem);
    const uint32_t sQ  = sb + ASM_Q;
    const uint32_t sK  = sb + ASM_K;
    const uint32_t sV  = sb + ASM_V;

    const int tid  = threadIdx.x;
    const int wid  = tid >> 5;
    const int lane = tid & 31;
    const int bh = blockIdx.y;
    const int batch = bh / NHEADS;
    const int h = bh % NHEADS;
    const int qrow0 = batch * S_ + blockIdx.x * 128;

    // ---- loads (one-shot, cp.async) ----
    {
        const __half* qp = g_q + (size_t)qrow0 * H_ + h * DH;
        #pragma unroll
        for (int i = 0; i < 4; i++) {
            int idx = i * 256 + tid;            // 0..1023
            int row = idx >> 3, c = idx & 7;
            CP_ASYNC_16(sQ + swz128(row, c), qp + (size_t)row * H_ + c * 8);
        }
        const __half* kp = g_k + (size_t)batch * LPAD * H_ + h * DH;
        for (int idx = tid; idx < LPAD * 8; idx += 256) {
            int row = idx >> 3, c = idx & 7;
            CP_ASYNC_16(sK + swz128(row, c), kp + (size_t)row * H_ + c * 8);
        }
        const __half* vp = g_vt + ((size_t)batch * H_ + h * DH) * LPAD2;
        for (int idx = tid; idx < 64 * 14; idx += 256) {
            int row = idx / 14, c = idx % 14;
            CP_ASYNC_16(sV + (uint32_t)(row * 240 + c * 16),
                        vp + (size_t)row * LPAD2 + c * 8);
        }
        CP_COMMIT();
    }
    CP_WAIT0();
    __syncthreads();

    const int gid = lane >> 2, tig = lane & 3;
    const int a_row_off = (lane & 7) + ((lane >> 3) & 1) * 8;
    const int a_half    = lane >> 4;
    const int b_row_off = (lane & 7) + ((lane >> 4) & 1) * 8;
    const int b_half    = (lane >> 3) & 1;

    // q fragments: 4 k-steps (single fp16)
    uint32_t fQ[4][4];
    #pragma unroll
    for (int ks = 0; ks < 4; ks++) {
        int row = wid * 16 + a_row_off;
        uint32_t ad = swz128(row, ks * 2 + a_half);
        ldsm_x4(fQ[ks][0], fQ[ks][1], fQ[ks][2], fQ[ks][3], sQ + ad);
    }

    float acc[8][4];
    #pragma unroll
    for (int nt = 0; nt < 8; nt++)
        #pragma unroll
        for (int c = 0; c < 4; c++) acc[nt][c] = 0.f;
    float rs0 = 0.f, rs1 = 0.f;
    const float scale = 0.125f;

    #pragma unroll
    for (int kt = 0; kt < 7; kt++) {       // l tiles of 16 (0..111)
        float c0[4] = {0.f, 0.f, 0.f, 0.f};
        float c1[4] = {0.f, 0.f, 0.f, 0.f};
        #pragma unroll
        for (int ks = 0; ks < 4; ks++) {
            int row = kt * 16 + b_row_off;
            uint32_t bd = swz128(row, ks * 2 + b_half);
            uint32_t kb0, kb1, kb2, kb3;
            ldsm_x4(kb0, kb1, kb2, kb3, sK + bd);
            mma_f16(c0, fQ[ks], kb0, kb1);
            mma_f16(c1, fQ[ks], kb2, kb3);
        }
        float e0[4], e1[4];
        #pragma unroll
        for (int j = 0; j < 4; j++) {
            e0[j] = __expf(c0[j] * scale);
            e1[j] = __expf(c1[j] * scale);
        }
        if (kt == 6) {   // n-tile 13: cols 104..111, mask col >= 109
            float m0v = (104 + 2 * tig <= 108) ? 1.f : 0.f;
            float m1v = (105 + 2 * tig <= 108) ? 1.f : 0.f;
            e1[0] *= m0v; e1[1] *= m1v; e1[2] *= m0v; e1[3] *= m1v;
        }
        rs0 += e0[0] + e0[1] + e1[0] + e1[1];
        rs1 += e0[2] + e0[3] + e1[2] + e1[3];
        uint32_t ah[4];
        ah[0] = h2_bits(__floats2half2_rn(e0[0], e0[1]));
        ah[1] = h2_bits(__floats2half2_rn(e0[2], e0[3]));
        ah[2] = h2_bits(__floats2half2_rn(e1[0], e1[1]));
        ah[3] = h2_bits(__floats2half2_rn(e1[2], e1[3]));
        #pragma unroll
        for (int g = 0; g < 4; g++) {
            uint32_t bd = (uint32_t)((g * 16 + b_row_off) * 240 +
                                     (kt * 2 + b_half) * 16);
            uint32_t vb0, vb1, vb2, vb3;
            ldsm_x4(vb0, vb1, vb2, vb3, sV + bd);
            mma_f16(acc[g * 2 + 0], ah, vb0, vb1);
            mma_f16(acc[g * 2 + 1], ah, vb2, vb3);
        }
    }

    rs0 += __shfl_xor_sync(0xffffffffu, rs0, 1);
    rs0 += __shfl_xor_sync(0xffffffffu, rs0, 2);
    rs1 += __shfl_xor_sync(0xffffffffu, rs1, 1);
    rs1 += __shfl_xor_sync(0xffffffffu, rs1, 2);
    const float inv0 = 1.f / rs0;
    const float inv1 = 1.f / rs1;

    const int r0 = qrow0 + wid * 16 + gid;
    #pragma unroll
    for (int nt = 0; nt < 8; nt++) {
        int col = h * DH + nt * 8 + tig * 2;
        *(__half2*)(g_att + (size_t)r0 * H_ + col) =
            __floats2half2_rn(acc[nt][0] * inv0, acc[nt][1] * inv0);
        *(__half2*)(g_att + (size_t)(r0 + 8) * H_ + col) =
            __floats2half2_rn(acc[nt][2] * inv1, acc[nt][3] * inv1);
    }
}

// ---------------------------------------------------------------------------
// Side streams + events for fork/join inside graph capture (host objects).
// ---------------------------------------------------------------------------
struct SideStreams {
    cudaStream_t s1, s2;
    cudaEvent_t ef1, ef2, e_kv, e_w;
    SideStreams() {
        cudaStreamCreateWithFlags(&s1, cudaStreamNonBlocking);
        cudaStreamCreateWithFlags(&s2, cudaStreamNonBlocking);
        cudaEventCreateWithFlags(&ef1, cudaEventDisableTiming);
        cudaEventCreateWithFlags(&ef2, cudaEventDisableTiming);
        cudaEventCreateWithFlags(&e_kv, cudaEventDisableTiming);
        cudaEventCreateWithFlags(&e_w, cudaEventDisableTiming);
    }
};
static SideStreams& side() { static SideStreams s; return s; }

// ---------------------------------------------------------------------------
extern "C" void kernel_launch(void* const* d_in, const int* in_sizes, int n_in,
                              void* d_out, int out_size)
{
    (void)in_sizes; (void)n_in; (void)out_size;
    const float* hs    = (const float*)d_in[0];
    const float* ehs   = (const float*)d_in[1];
    const float* idemb = (const float*)d_in[2];
    const float* Wq    = (const float*)d_in[3];
    const float* Wk    = (const float*)d_in[4];
    const float* Wv    = (const float*)d_in[5];
    const float* Wid_k = (const float*)d_in[6];
    const float* Wid_v = (const float*)d_in[7];
    const float* Wout  = (const float*)d_in[8];
    const float* bout  = (const float*)d_in[9];
    float* out = (float*)d_out;

    const int attn_smem = ASM_TOT;            // 46,080 B
    const int gemm_smem = NSTAGE * STAGE_B;   // 98,304 B
    cudaFuncSetAttribute(attn_kernel,
                         cudaFuncAttributeMaxDynamicSharedMemorySize, attn_smem);
    cudaFuncSetAttribute(gemm_hmma<0>,
                         cudaFuncAttributeMaxDynamicSharedMemorySize, gemm_smem);
    cudaFuncSetAttribute(gemm_hmma<1>,
                         cudaFuncAttributeMaxDynamicSharedMemorySize, gemm_smem);

    SideStreams& ss = side();

    // Fork: kv on s1, weight transpose on s2, concurrent with critical path.
    cudaEventRecord(ss.ef1, 0);
    cudaStreamWaitEvent(ss.s1, ss.ef1, 0);
    cudaEventRecord(ss.ef2, 0);
    cudaStreamWaitEvent(ss.s2, ss.ef2, 0);

    kv_kernel<<<dim3(H_ / 64, (B_ * T_ + 63) / 64, 4), 256, 0, ss.s1>>>(
        ehs, idemb, Wk, Wv, Wid_k, Wid_v);
    cudaEventRecord(ss.e_kv, ss.s1);

    tsplit_kernel<<<dim3(H_ / 32, H_ / 32, 2), dim3(32, 8), 0, ss.s2>>>(Wq, Wout);
    cudaEventRecord(ss.e_w, ss.s2);

    // Main stream: hidden_states -> fp16
    split_kernel<<<(ROWS * H_ / 4 + 255) / 256, 256>>>(hs);

    // gemm0 needs g_wq (join s2)
    cudaStreamWaitEvent(0, ss.e_w, 0);
    gemm_hmma<0><<<dim3(GN / 128, ROWS / 128), 256, gemm_smem>>>(nullptr, nullptr);

    // attention needs K/V (join s1)
    cudaStreamWaitEvent(0, ss.e_kv, 0);
    attn_kernel<<<dim3(S_ / 128, B_ * NHEADS), 256, attn_smem>>>();

    // out = att @ Wout + bout
    gemm_hmma<1><<<dim3(GN / 128, ROWS / 128), 256, gemm_smem>>>(bout, out);
}